// round 9
// baseline (speedup 1.0000x reference)
#include <cuda_runtime.h>
#include <cuda_fp16.h>
#include <math.h>
#include <stdint.h>

// Problem constants
#define B_    2
#define S_    2048
#define D_    2048
#define H_    16
#define HD_   128
#define M_TOK (B_ * S_)          // 4096 tokens
#define QKV_N (3 * H_ * HD_)     // 6144
#define DM_   (H_ * HD_)         // 2048

// ---------------------------------------------------------------------------
// Scratch (__device__ globals; no allocation allowed)
// ---------------------------------------------------------------------------
__device__ float g_cos[S_ * (HD_ / 2)];
__device__ float g_sin[S_ * (HD_ / 2)];
__device__ __half g_Ah[(size_t)M_TOK * D_];        // GEMM A hi (x, later O)
__device__ __half g_Al[(size_t)M_TOK * D_];        // GEMM A lo
__device__ __half g_Bh[(size_t)QKV_N * D_];        // W_qkv^T rounded [N][K]
__device__ __half g_Woh[(size_t)DM_ * D_];         // W_o^T rounded [N][K]
__device__ __half g_Qh[(size_t)M_TOK * DM_];       // [b,h,s,hd] (pre-scaled)
__device__ __half g_Ql[(size_t)M_TOK * DM_];
__device__ __half g_Kh[(size_t)M_TOK * DM_];       // rounded only
__device__ __half g_Vth[(size_t)M_TOK * DM_];      // [b,h,hd,s] rounded only

// ---------------------------------------------------------------------------
// PTX helpers (arch-generic only; compute_103 target rejects tcgen05)
// ---------------------------------------------------------------------------
__device__ __forceinline__ uint32_t smem_u32(const void* p) {
    uint32_t a;
    asm("{ .reg .u64 t; cvta.to.shared.u64 t, %1; cvt.u32.u64 %0, t; }"
        : "=r"(a) : "l"(p));
    return a;
}
#define CP16(dst, src) \
    asm volatile("cp.async.cg.shared.global [%0], [%1], 16;" :: "r"(dst), "l"(src) : "memory")
#define CP_COMMIT() asm volatile("cp.async.commit_group;" ::: "memory")
#define CP_WAIT(n)  asm volatile("cp.async.wait_group %0;" :: "n"(n) : "memory")

__device__ __forceinline__ void ldsm4(uint32_t* r, uint32_t addr) {
    asm volatile("ldmatrix.sync.aligned.m8n8.x4.shared.b16 {%0,%1,%2,%3}, [%4];"
                 : "=r"(r[0]), "=r"(r[1]), "=r"(r[2]), "=r"(r[3]) : "r"(addr));
}
__device__ __forceinline__ void mma16816(float* c, const uint32_t* a, const uint32_t* b) {
    asm volatile(
        "mma.sync.aligned.m16n8k16.row.col.f32.f16.f16.f32 "
        "{%0,%1,%2,%3}, {%4,%5,%6,%7}, {%8,%9}, {%0,%1,%2,%3};"
        : "+f"(c[0]), "+f"(c[1]), "+f"(c[2]), "+f"(c[3])
        : "r"(a[0]), "r"(a[1]), "r"(a[2]), "r"(a[3]), "r"(b[0]), "r"(b[1]));
}
__device__ __forceinline__ uint32_t pack_h2(float x, float y) {
    __half2 t = __floats2half2_rn(x, y);
    return *(uint32_t*)&t;
}

// ---------------------------------------------------------------------------
// GEMM tiling constants (fp16x2: Ah,Al split; B rounded)
// CTA 128x128, BK=64, 3 smem tiles/stage -> 110592B, 2 CTAs/SM.
// ---------------------------------------------------------------------------
#define GSTR  72
#define TILE_E (128 * GSTR)
#define STG_E  (3 * TILE_E)
#define GEMM_SMEM (2 * STG_E * 2)      // 110592 bytes

// Shared mainloop: computes acc for one 128x128 tile of A @ B^T (K = D_).
#define GEMM_MAINLOOP(Ah, Al, Bh, KDIM)                                            \
    auto load_chunk = [&](int stage, int kc) {                                     \
        _Pragma("unroll")                                                          \
        for (int j = 0; j < 12; ++j) {                                             \
            int s = tid + j * 256;                                                 \
            int tile = s >> 10;                                                    \
            int r = (s >> 3) & 127;                                                \
            int c = s & 7;                                                         \
            const __half* p = (tile == 0) ? Ah : (tile == 1) ? Al : Bh;            \
            int rb = (tile < 2) ? bm : bn;                                         \
            const __half* src = p + (size_t)(rb + r) * (KDIM) + kc + c * 8;        \
            uint32_t dst = sbase + (uint32_t)(stage * STG_E + tile * TILE_E +      \
                                              r * GSTR + c * 8) * 2u;              \
            CP16(dst, src);                                                        \
        }                                                                          \
    };                                                                             \
    const int NC = (KDIM) / 64;                                                    \
    load_chunk(0, 0);                                                              \
    CP_COMMIT();                                                                   \
    for (int i = 0; i < NC; ++i) {                                                 \
        if (i + 1 < NC) {                                                          \
            load_chunk((i + 1) & 1, (i + 1) * 64);                                 \
            CP_COMMIT();                                                           \
            CP_WAIT(1);                                                            \
        } else {                                                                   \
            CP_WAIT(0);                                                            \
        }                                                                          \
        __syncthreads();                                                           \
        const uint32_t sA  = sbase + (uint32_t)((i & 1) * STG_E) * 2u;             \
        const uint32_t dAl = TILE_E * 2u;                                          \
        const uint32_t dB  = 2u * TILE_E * 2u;                                     \
        _Pragma("unroll")                                                          \
        for (int ks = 0; ks < 64; ks += 16) {                                      \
            uint32_t ah[2][4], al[2][4], bh[8][2];                                 \
            _Pragma("unroll")                                                      \
            for (int mt = 0; mt < 2; ++mt) {                                       \
                uint32_t ra = sA + (uint32_t)((wm + mt * 16 + (lane & 15)) * GSTR +\
                                              ks + (lane >> 4) * 8) * 2u;          \
                ldsm4(ah[mt], ra);                                                 \
                ldsm4(al[mt], ra + dAl);                                           \
            }                                                                      \
            _Pragma("unroll")                                                      \
            for (int p = 0; p < 4; ++p) {                                          \
                uint32_t rb = sA + dB + (uint32_t)((wn + p * 16 + (lane & 15)) * GSTR + \
                                                   ks + (lane >> 4) * 8) * 2u;     \
                uint32_t t[4];                                                     \
                ldsm4(t, rb);                                                      \
                bh[2 * p][0] = t[0]; bh[2 * p + 1][0] = t[1];                      \
                bh[2 * p][1] = t[2]; bh[2 * p + 1][1] = t[3];                      \
            }                                                                      \
            _Pragma("unroll")                                                      \
            for (int mt = 0; mt < 2; ++mt)                                         \
                _Pragma("unroll")                                                  \
                for (int nt = 0; nt < 8; ++nt) mma16816(acc[mt][nt], ah[mt], bh[nt]); \
            _Pragma("unroll")                                                      \
            for (int mt = 0; mt < 2; ++mt)                                         \
                _Pragma("unroll")                                                  \
                for (int nt = 0; nt < 8; ++nt) mma16816(acc[mt][nt], al[mt], bh[nt]); \
        }                                                                          \
        __syncthreads();                                                           \
    }

// ---------------------------------------------------------------------------
// GEMM1 fused: qkv = x @ W_qkv^T with RoPE + operand-layout epilogue.
// N-tile 128 == one head of q, k, or v. Epilogue stages acc in smem fp32
// (stride 129, conflict-free) then writes Qh/Ql (RoPE+scale+split),
// Kh (RoPE+round), or Vth (transpose+round).
// ---------------------------------------------------------------------------
__global__ __launch_bounds__(256) void gemm1_fused_kernel(
    const __half* __restrict__ Ah, const __half* __restrict__ Al,
    const __half* __restrict__ Bh,
    const float* __restrict__ ct, const float* __restrict__ st,
    __half* __restrict__ Qh, __half* __restrict__ Ql,
    __half* __restrict__ Kh, __half* __restrict__ Vth)
{
    extern __shared__ __half sm[];
    const uint32_t sbase = smem_u32(sm);
    const int tid  = threadIdx.x;
    const int lane = tid & 31;
    const int wid  = tid >> 5;
    const int bm = blockIdx.y * 128;
    const int bn = blockIdx.x * 128;
    const int wm = (wid & 3) * 32;
    const int wn = (wid >> 2) * 64;

    float acc[2][8][4];
#pragma unroll
    for (int mt = 0; mt < 2; ++mt)
#pragma unroll
        for (int nt = 0; nt < 8; ++nt)
#pragma unroll
            for (int v = 0; v < 4; ++v) acc[mt][nt][v] = 0.f;

    GEMM_MAINLOOP(Ah, Al, Bh, D_)

    // ---- epilogue: acc -> smem fp32 (stride 129) ----
    float* sf = (float*)sm;
#pragma unroll
    for (int mt = 0; mt < 2; ++mt) {
        int row = wm + mt * 16 + (lane >> 2);
#pragma unroll
        for (int nt = 0; nt < 8; ++nt) {
            int col = wn + nt * 8 + (lane & 3) * 2;
            sf[row * 129 + col]           = acc[mt][nt][0];
            sf[row * 129 + col + 1]       = acc[mt][nt][1];
            sf[(row + 8) * 129 + col]     = acc[mt][nt][2];
            sf[(row + 8) * 129 + col + 1] = acc[mt][nt][3];
        }
    }
    __syncthreads();

    const int t    = bn >> 7;       // 0..47: head-slot
    const int h    = t & 15;
    const int kind = t >> 4;        // 0=q 1=k 2=v
    const int b    = bm >> 11;      // tile never crosses batch boundary
    const int s0   = bm & (S_ - 1);

    if (kind < 2) {
        // RoPE on (d, d+64) pairs
        for (int idx = tid; idx < 128 * 64; idx += 256) {
            int r = idx >> 6, d = idx & 63;
            float lo_v = sf[r * 129 + d];
            float hi_v = sf[r * 129 + d + 64];
            int s = s0 + r;
            float c  = ct[(s << 6) + d];
            float sn = st[(s << 6) + d];
            float e0 = lo_v * c - hi_v * sn;
            float e1 = hi_v * c + lo_v * sn;
            size_t dst = ((size_t)(b * H_ + h) * S_ + s) * HD_ + d;
            if (kind == 0) {
                e0 *= 0.08838834764831845f;
                e1 *= 0.08838834764831845f;
                __half h0 = __float2half_rn(e0);
                __half h1 = __float2half_rn(e1);
                Qh[dst]      = h0;
                Qh[dst + 64] = h1;
                Ql[dst]      = __float2half_rn(e0 - __half2float(h0));
                Ql[dst + 64] = __float2half_rn(e1 - __half2float(h1));
            } else {
                Kh[dst]      = __float2half_rn(e0);
                Kh[dst + 64] = __float2half_rn(e1);
            }
        }
    } else {
        // V: transpose to [bh][hd][s]
        __half* vdst = Vth + (size_t)(b * H_ + h) * HD_ * S_;
        for (int idx = tid; idx < 128 * 128; idx += 256) {
            int r = idx & 127, d = idx >> 7;
            vdst[(size_t)d * S_ + s0 + r] = __float2half_rn(sf[r * 129 + d]);
        }
    }
}

// ---------------------------------------------------------------------------
// GEMM2: out = O @ W_o^T (fp32 output)
// ---------------------------------------------------------------------------
__global__ __launch_bounds__(256) void gemm_mma_kernel(
    const __half* __restrict__ Ah, const __half* __restrict__ Al,
    const __half* __restrict__ Bh,
    float* __restrict__ C, int M, int N, int K)
{
    extern __shared__ __half sm[];
    const uint32_t sbase = smem_u32(sm);
    const int tid  = threadIdx.x;
    const int lane = tid & 31;
    const int wid  = tid >> 5;
    const int bm = blockIdx.y * 128;
    const int bn = blockIdx.x * 128;
    const int wm = (wid & 3) * 32;
    const int wn = (wid >> 2) * 64;

    float acc[2][8][4];
#pragma unroll
    for (int mt = 0; mt < 2; ++mt)
#pragma unroll
        for (int nt = 0; nt < 8; ++nt)
#pragma unroll
            for (int v = 0; v < 4; ++v) acc[mt][nt][v] = 0.f;

    GEMM_MAINLOOP(Ah, Al, Bh, K)

#pragma unroll
    for (int mt = 0; mt < 2; ++mt) {
        int row = bm + wm + mt * 16 + (lane >> 2);
#pragma unroll
        for (int nt = 0; nt < 8; ++nt) {
            int col = bn + wn + nt * 8 + (lane & 3) * 2;
            *(float2*)&C[(size_t)row * N + col] =
                make_float2(acc[mt][nt][0], acc[mt][nt][1]);
            *(float2*)&C[(size_t)(row + 8) * N + col] =
                make_float2(acc[mt][nt][2], acc[mt][nt][3]);
        }
    }
}

// ---------------------------------------------------------------------------
// fp32 -> fp16 hi/lo split (A-side)
// ---------------------------------------------------------------------------
__global__ void conv_split_kernel(const float* __restrict__ X,
                                  __half* __restrict__ Xh,
                                  __half* __restrict__ Xl, int n4)
{
    int i = blockIdx.x * blockDim.x + threadIdx.x;
    if (i >= n4) return;
    float4 v = *(const float4*)(X + (size_t)i * 4);
    __half2 h01 = __floats2half2_rn(v.x, v.y);
    __half2 h23 = __floats2half2_rn(v.z, v.w);
    float2 f01 = __half22float2(h01);
    float2 f23 = __half22float2(h23);
    __half2 l01 = __floats2half2_rn(v.x - f01.x, v.y - f01.y);
    __half2 l23 = __floats2half2_rn(v.z - f23.x, v.w - f23.y);
    *(__half2*)(Xh + (size_t)i * 4)     = h01;
    *(__half2*)(Xh + (size_t)i * 4 + 2) = h23;
    *(__half2*)(Xl + (size_t)i * 4)     = l01;
    *(__half2*)(Xl + (size_t)i * 4 + 2) = l23;
}

// ---------------------------------------------------------------------------
// fp32 W[R,C] -> transposed fp16 (rounded) T[C,R]
// ---------------------------------------------------------------------------
__global__ __launch_bounds__(256) void conv_tround_kernel(
    const float* __restrict__ W, int R, int C, __half* __restrict__ Th)
{
    __shared__ float t[32][33];
    const int c0 = blockIdx.x * 32, r0 = blockIdx.y * 32;
    const int tx = threadIdx.x & 31, ty = threadIdx.x >> 5;
#pragma unroll
    for (int i = 0; i < 32; i += 8)
        t[ty + i][tx] = W[(size_t)(r0 + ty + i) * C + c0 + tx];
    __syncthreads();
#pragma unroll
    for (int i = 0; i < 32; i += 8)
        Th[(size_t)(c0 + ty + i) * R + r0 + tx] = __float2half_rn(t[tx][ty + i]);
}

// ---------------------------------------------------------------------------
// RoPE table
// ---------------------------------------------------------------------------
__global__ void rope_table_kernel(float* __restrict__ ct, float* __restrict__ st)
{
    int idx = blockIdx.x * blockDim.x + threadIdx.x;
    if (idx >= S_ * 64) return;
    int d = idx & 63;
    int s = idx >> 6;
    float inv_freq = 1.0f / powf(10000.0f, (float)d * (1.0f / 64.0f));
    float ang = (float)s * inv_freq;
    ct[idx] = (float)cos((double)ang);
    st[idx] = (float)sin((double)ang);
}

// ---------------------------------------------------------------------------
// Flash attention, fp16x2 mma.sync, Q-tile 128, double-buffered KV (64/tile).
// ---------------------------------------------------------------------------
#define QSTR 136
#define VSTR 72
#define QH_OFF 0u
#define QL_OFF 34816u
#define KV_BASE 69632u
#define KV_STG  35840u
#define KH_R 0u
#define VH_R 17408u
#define ATT_SMEM (KV_BASE + 2u * KV_STG)   // 141312 bytes

__global__ __launch_bounds__(256) void attn_mma_kernel(
    const __half* __restrict__ Qh, const __half* __restrict__ Ql,
    const __half* __restrict__ Kh, const __half* __restrict__ Vth,
    __half* __restrict__ Oh, __half* __restrict__ Ol)
{
    extern __shared__ char asm_[];
    const uint32_t sb = smem_u32(asm_);
    const int tid  = threadIdx.x;
    const int lane = tid & 31;
    const int wid  = tid >> 5;
    const int qb = (int)(gridDim.x - 1) - (int)blockIdx.x;   // heavy first
    const int h  = blockIdx.y;
    const int b  = blockIdx.z;
    const int bh = b * H_ + h;
    const int q0 = qb * 128;
    const int wq = wid * 16;

    const __half* k_h = Kh + ((size_t)bh * S_) * HD_;
    const __half* v_h = Vth + (size_t)bh * HD_ * S_;

    {
        const __half* q_h = Qh + ((size_t)bh * S_ + q0) * HD_;
        const __half* q_l = Ql + ((size_t)bh * S_ + q0) * HD_;
#pragma unroll
        for (int j = 0; j < 16; ++j) {
            int s = tid + j * 256;
            int hi = s < 2048;
            int u = s & 2047;
            int r = u >> 4, c = u & 15;
            const __half* src = (hi ? q_h : q_l) + (size_t)r * HD_ + c * 8;
            CP16(sb + (hi ? QH_OFF : QL_OFF) + (uint32_t)(r * QSTR + c * 8) * 2u, src);
        }
    }
    CP_COMMIT();

    auto load_kv = [&](int stage, int kv0) {
        const uint32_t st = KV_BASE + (uint32_t)stage * KV_STG;
#pragma unroll
        for (int j = 0; j < 8; ++j) {
            int s = tid + j * 256;
            if (s < 1024) {
                int r = s >> 4, c = s & 15;
                const __half* src = k_h + (size_t)(kv0 + r) * HD_ + c * 8;
                CP16(sb + st + KH_R + (uint32_t)(r * QSTR + c * 8) * 2u, src);
            } else {
                int u = s - 1024;
                int r = u >> 3, c = u & 7;
                const __half* src = v_h + (size_t)r * S_ + kv0 + c * 8;
                CP16(sb + st + VH_R + (uint32_t)(r * VSTR + c * 8) * 2u, src);
            }
        }
    };

    const int nkb = 2 * (qb + 1);
    load_kv(0, 0);
    CP_COMMIT();

    float acc[16][4];
#pragma unroll
    for (int nt = 0; nt < 16; ++nt)
#pragma unroll
        for (int v = 0; v < 4; ++v) acc[nt][v] = 0.f;
    float m0 = -INFINITY, m1 = -INFINITY, l0 = 0.f, l1 = 0.f;

    const int r0 = lane >> 2;
    const int rg0 = q0 + wq + r0;

    for (int kb = 0; kb < nkb; ++kb) {
        const int kv0 = kb * 64;
        __syncthreads();
        if (kb + 1 < nkb) {
            load_kv((kb + 1) & 1, kv0 + 64);
            CP_COMMIT();
            CP_WAIT(1);
        } else {
            CP_WAIT(0);
        }
        __syncthreads();

        const uint32_t skv = sb + KV_BASE + (uint32_t)(kb & 1) * KV_STG;

        float sc[8][4];
#pragma unroll
        for (int nt = 0; nt < 8; ++nt)
#pragma unroll
            for (int v = 0; v < 4; ++v) sc[nt][v] = 0.f;

#pragma unroll
        for (int ks = 0; ks < 8; ++ks) {
            uint32_t a_h[4], a_l[4], b_h[8][2];
            uint32_t ra = sb + QH_OFF + (uint32_t)((wq + (lane & 15)) * QSTR +
                                                   ks * 16 + (lane >> 4) * 8) * 2u;
            ldsm4(a_h, ra);
            ldsm4(a_l, ra + QL_OFF);
#pragma unroll
            for (int p = 0; p < 4; ++p) {
                uint32_t rb = skv + KH_R + (uint32_t)((p * 16 + (lane & 15)) * QSTR +
                                                      ks * 16 + (lane >> 4) * 8) * 2u;
                uint32_t t[4];
                ldsm4(t, rb);
                b_h[2 * p][0] = t[0]; b_h[2 * p + 1][0] = t[1];
                b_h[2 * p][1] = t[2]; b_h[2 * p + 1][1] = t[3];
            }
#pragma unroll
            for (int nt = 0; nt < 8; ++nt) mma16816(sc[nt], a_h, b_h[nt]);
#pragma unroll
            for (int nt = 0; nt < 8; ++nt) mma16816(sc[nt], a_l, b_h[nt]);
        }

        if (kv0 + 63 > q0 + wq) {
#pragma unroll
            for (int nt = 0; nt < 8; ++nt) {
                int c0 = kv0 + nt * 8 + (lane & 3) * 2;
                if (c0     > rg0)     sc[nt][0] = -INFINITY;
                if (c0 + 1 > rg0)     sc[nt][1] = -INFINITY;
                if (c0     > rg0 + 8) sc[nt][2] = -INFINITY;
                if (c0 + 1 > rg0 + 8) sc[nt][3] = -INFINITY;
            }
        }

        float mx0 = -INFINITY, mx1 = -INFINITY;
#pragma unroll
        for (int nt = 0; nt < 8; ++nt) {
            mx0 = fmaxf(mx0, fmaxf(sc[nt][0], sc[nt][1]));
            mx1 = fmaxf(mx1, fmaxf(sc[nt][2], sc[nt][3]));
        }
        mx0 = fmaxf(mx0, __shfl_xor_sync(0xffffffffu, mx0, 1));
        mx0 = fmaxf(mx0, __shfl_xor_sync(0xffffffffu, mx0, 2));
        mx1 = fmaxf(mx1, __shfl_xor_sync(0xffffffffu, mx1, 1));
        mx1 = fmaxf(mx1, __shfl_xor_sync(0xffffffffu, mx1, 2));
        float m0n = fmaxf(m0, mx0), m1n = fmaxf(m1, mx1);
        float al0 = __expf(m0 - m0n), al1 = __expf(m1 - m1n);
        float ps0 = 0.f, ps1 = 0.f;
#pragma unroll
        for (int nt = 0; nt < 8; ++nt) {
            sc[nt][0] = __expf(sc[nt][0] - m0n);
            sc[nt][1] = __expf(sc[nt][1] - m0n);
            sc[nt][2] = __expf(sc[nt][2] - m1n);
            sc[nt][3] = __expf(sc[nt][3] - m1n);
            ps0 += sc[nt][0] + sc[nt][1];
            ps1 += sc[nt][2] + sc[nt][3];
        }
        ps0 += __shfl_xor_sync(0xffffffffu, ps0, 1);
        ps0 += __shfl_xor_sync(0xffffffffu, ps0, 2);
        ps1 += __shfl_xor_sync(0xffffffffu, ps1, 1);
        ps1 += __shfl_xor_sync(0xffffffffu, ps1, 2);
        l0 = l0 * al0 + ps0;
        l1 = l1 * al1 + ps1;
        m0 = m0n; m1 = m1n;
#pragma unroll
        for (int nt = 0; nt < 16; ++nt) {
            acc[nt][0] *= al0; acc[nt][1] *= al0;
            acc[nt][2] *= al1; acc[nt][3] *= al1;
        }

        uint32_t phk[4][4], plk[4][4];
#pragma unroll
        for (int kt = 0; kt < 4; ++kt) {
#pragma unroll
            for (int half = 0; half < 2; ++half) {
                int j = 2 * kt + half;
                uint32_t p01 = pack_h2(sc[j][0], sc[j][1]);
                uint32_t p23 = pack_h2(sc[j][2], sc[j][3]);
                float2 f01 = __half22float2(*(__half2*)&p01);
                float2 f23 = __half22float2(*(__half2*)&p23);
                phk[kt][half * 2 + 0] = p01;
                phk[kt][half * 2 + 1] = p23;
                plk[kt][half * 2 + 0] = pack_h2(sc[j][0] - f01.x, sc[j][1] - f01.y);
                plk[kt][half * 2 + 1] = pack_h2(sc[j][2] - f23.x, sc[j][3] - f23.y);
            }
        }

#pragma unroll
        for (int kt = 0; kt < 4; ++kt) {
#pragma unroll
            for (int hlf = 0; hlf < 2; ++hlf) {
                uint32_t bvh[8][2];
#pragma unroll
                for (int p = 0; p < 4; ++p) {
                    uint32_t rb = skv + VH_R +
                        (uint32_t)((hlf * 64 + p * 16 + (lane & 15)) * VSTR +
                                   kt * 16 + (lane >> 4) * 8) * 2u;
                    uint32_t t[4];
                    ldsm4(t, rb);
                    bvh[2 * p][0] = t[0]; bvh[2 * p + 1][0] = t[1];
                    bvh[2 * p][1] = t[2]; bvh[2 * p + 1][1] = t[3];
                }
#pragma unroll
                for (int nt = 0; nt < 8; ++nt) mma16816(acc[hlf * 8 + nt], phk[kt], bvh[nt]);
#pragma unroll
                for (int nt = 0; nt < 8; ++nt) mma16816(acc[hlf * 8 + nt], plk[kt], bvh[nt]);
            }
        }
    }

    float inv0 = 1.f / l0, inv1 = 1.f / l1;
    size_t tok0 = (size_t)b * S_ + q0 + wq + r0;
#pragma unroll
    for (int nt = 0; nt < 16; ++nt) {
        int col = h * HD_ + nt * 8 + (lane & 3) * 2;
        {
            float o0 = acc[nt][0] * inv0, o1 = acc[nt][1] * inv0;
            uint32_t hi = pack_h2(o0, o1);
            float2 f = __half22float2(*(__half2*)&hi);
            uint32_t lo = pack_h2(o0 - f.x, o1 - f.y);
            *(uint32_t*)&Oh[tok0 * DM_ + col] = hi;
            *(uint32_t*)&Ol[tok0 * DM_ + col] = lo;
        }
        {
            float o0 = acc[nt][2] * inv1, o1 = acc[nt][3] * inv1;
            uint32_t hi = pack_h2(o0, o1);
            float2 f = __half22float2(*(__half2*)&hi);
            uint32_t lo = pack_h2(o0 - f.x, o1 - f.y);
            *(uint32_t*)&Oh[(tok0 + 8) * DM_ + col] = hi;
            *(uint32_t*)&Ol[(tok0 + 8) * DM_ + col] = lo;
        }
    }
}

// ---------------------------------------------------------------------------
// Launch
// ---------------------------------------------------------------------------
extern "C" void kernel_launch(void* const* d_in, const int* in_sizes, int n_in,
                              void* d_out, int out_size)
{
    (void)in_sizes; (void)n_in; (void)out_size;
    const float* x     = (const float*)d_in[0];
    const float* W_qkv = (const float*)d_in[1];
    const float* W_o   = (const float*)d_in[2];
    float* out = (float*)d_out;

    float *ct, *st;
    __half *Ah, *Al, *Bh, *Woh, *Qh, *Ql, *Kh, *Vth;
    cudaGetSymbolAddress((void**)&ct,   g_cos);
    cudaGetSymbolAddress((void**)&st,   g_sin);
    cudaGetSymbolAddress((void**)&Ah,   g_Ah);
    cudaGetSymbolAddress((void**)&Al,   g_Al);
    cudaGetSymbolAddress((void**)&Bh,   g_Bh);
    cudaGetSymbolAddress((void**)&Woh,  g_Woh);
    cudaGetSymbolAddress((void**)&Qh,   g_Qh);
    cudaGetSymbolAddress((void**)&Ql,   g_Ql);
    cudaGetSymbolAddress((void**)&Kh,   g_Kh);
    cudaGetSymbolAddress((void**)&Vth,  g_Vth);

    cudaFuncSetAttribute(gemm1_fused_kernel,
                         cudaFuncAttributeMaxDynamicSharedMemorySize, GEMM_SMEM);
    cudaFuncSetAttribute(gemm_mma_kernel,
                         cudaFuncAttributeMaxDynamicSharedMemorySize, GEMM_SMEM);
    cudaFuncSetAttribute(attn_mma_kernel,
                         cudaFuncAttributeMaxDynamicSharedMemorySize, ATT_SMEM);

    rope_table_kernel<<<(S_ * 64 + 255) / 256, 256>>>(ct, st);

    conv_split_kernel<<<(M_TOK * D_ / 4 + 255) / 256, 256>>>(x, Ah, Al, M_TOK * D_ / 4);
    conv_tround_kernel<<<dim3(QKV_N / 32, D_ / 32), 256>>>(W_qkv, D_, QKV_N, Bh);
    conv_tround_kernel<<<dim3(DM_ / 32, D_ / 32), 256>>>(W_o, DM_, DM_, Woh);

    // fused qkv-projection + RoPE + attention-operand layout
    gemm1_fused_kernel<<<dim3(QKV_N / 128, M_TOK / 128), 256, GEMM_SMEM>>>(
        Ah, Al, Bh, ct, st, Qh, Ql, Kh, Vth);

    // causal flash attention -> writes Ah/Al (GEMM2 operand)
    attn_mma_kernel<<<dim3(S_ / 128, H_, B_), 256, ATT_SMEM>>>(
        Qh, Ql, Kh, Vth, Ah, Al);

    // out = O @ W_o
    gemm_mma_kernel<<<dim3(DM_ / 128, M_TOK / 128), 256, GEMM_SMEM>>>(
        Ah, Al, Woh, out, M_TOK, DM_, D_);
}

// round 10
// speedup vs baseline: 1.1614x; 1.1614x over previous
#include <cuda_runtime.h>
#include <cuda_fp16.h>
#include <math.h>
#include <stdint.h>

// Problem constants
#define B_    2
#define S_    2048
#define D_    2048
#define H_    16
#define HD_   128
#define M_TOK (B_ * S_)          // 4096 tokens
#define QKV_N (3 * H_ * HD_)     // 6144
#define DM_   (H_ * HD_)         // 2048

// ---------------------------------------------------------------------------
// Scratch (__device__ globals; no allocation allowed)
// ---------------------------------------------------------------------------
__device__ float g_cos[S_ * (HD_ / 2)];
__device__ float g_sin[S_ * (HD_ / 2)];
__device__ __half g_Ah[(size_t)M_TOK * D_];        // x hi; later O (rounded)
__device__ __half g_Al[(size_t)M_TOK * D_];        // x lo (GEMM1 only)
__device__ __half g_Bh[(size_t)QKV_N * D_];        // W_qkv^T rounded [N][K]
__device__ __half g_Woh[(size_t)DM_ * D_];         // W_o^T rounded [N][K]
__device__ __half g_Qh[(size_t)M_TOK * DM_];       // [b,h,s,hd] (pre-scaled)
__device__ __half g_Ql[(size_t)M_TOK * DM_];
__device__ __half g_Kh[(size_t)M_TOK * DM_];       // rounded only
__device__ __half g_Vth[(size_t)M_TOK * DM_];      // [b,h,hd,s] rounded only

// ---------------------------------------------------------------------------
// PTX helpers (arch-generic only; compute_103 target rejects tcgen05)
// ---------------------------------------------------------------------------
__device__ __forceinline__ uint32_t smem_u32(const void* p) {
    uint32_t a;
    asm("{ .reg .u64 t; cvta.to.shared.u64 t, %1; cvt.u32.u64 %0, t; }"
        : "=r"(a) : "l"(p));
    return a;
}
#define CP16(dst, src) \
    asm volatile("cp.async.cg.shared.global [%0], [%1], 16;" :: "r"(dst), "l"(src) : "memory")
#define CP_COMMIT() asm volatile("cp.async.commit_group;" ::: "memory")
#define CP_WAIT(n)  asm volatile("cp.async.wait_group %0;" :: "n"(n) : "memory")

__device__ __forceinline__ void ldsm4(uint32_t* r, uint32_t addr) {
    asm volatile("ldmatrix.sync.aligned.m8n8.x4.shared.b16 {%0,%1,%2,%3}, [%4];"
                 : "=r"(r[0]), "=r"(r[1]), "=r"(r[2]), "=r"(r[3]) : "r"(addr));
}
__device__ __forceinline__ void mma16816(float* c, const uint32_t* a, const uint32_t* b) {
    asm volatile(
        "mma.sync.aligned.m16n8k16.row.col.f32.f16.f16.f32 "
        "{%0,%1,%2,%3}, {%4,%5,%6,%7}, {%8,%9}, {%0,%1,%2,%3};"
        : "+f"(c[0]), "+f"(c[1]), "+f"(c[2]), "+f"(c[3])
        : "r"(a[0]), "r"(a[1]), "r"(a[2]), "r"(a[3]), "r"(b[0]), "r"(b[1]));
}
__device__ __forceinline__ uint32_t pack_h2(float x, float y) {
    __half2 t = __floats2half2_rn(x, y);
    return *(uint32_t*)&t;
}

// ---------------------------------------------------------------------------
// GEMM tiling constants
// ---------------------------------------------------------------------------
#define GSTR  72
#define TILE_E (128 * GSTR)
#define STG_E  (3 * TILE_E)
#define GEMM_SMEM (2 * STG_E * 2)        // 110592 B (GEMM1: Ah,Al,Bh)
#define STG2_E (2 * TILE_E)
#define GEMM2_SMEM (2 * STG2_E * 2)      // 73728 B  (GEMM2: Ah,Bh)

// Shared mainloop for split-A GEMM (Ah+Al vs Bh): acc for one 128x128 tile.
#define GEMM_MAINLOOP(Ah, Al, Bh, KDIM)                                            \
    auto load_chunk = [&](int stage, int kc) {                                     \
        _Pragma("unroll")                                                          \
        for (int j = 0; j < 12; ++j) {                                             \
            int s = tid + j * 256;                                                 \
            int tile = s >> 10;                                                    \
            int r = (s >> 3) & 127;                                                \
            int c = s & 7;                                                         \
            const __half* p = (tile == 0) ? Ah : (tile == 1) ? Al : Bh;            \
            int rb = (tile < 2) ? bm : bn;                                         \
            const __half* src = p + (size_t)(rb + r) * (KDIM) + kc + c * 8;        \
            uint32_t dst = sbase + (uint32_t)(stage * STG_E + tile * TILE_E +      \
                                              r * GSTR + c * 8) * 2u;              \
            CP16(dst, src);                                                        \
        }                                                                          \
    };                                                                             \
    const int NC = (KDIM) / 64;                                                    \
    load_chunk(0, 0);                                                              \
    CP_COMMIT();                                                                   \
    for (int i = 0; i < NC; ++i) {                                                 \
        if (i + 1 < NC) {                                                          \
            load_chunk((i + 1) & 1, (i + 1) * 64);                                 \
            CP_COMMIT();                                                           \
            CP_WAIT(1);                                                            \
        } else {                                                                   \
            CP_WAIT(0);                                                            \
        }                                                                          \
        __syncthreads();                                                           \
        const uint32_t sA  = sbase + (uint32_t)((i & 1) * STG_E) * 2u;             \
        const uint32_t dAl = TILE_E * 2u;                                          \
        const uint32_t dB  = 2u * TILE_E * 2u;                                     \
        _Pragma("unroll")                                                          \
        for (int ks = 0; ks < 64; ks += 16) {                                      \
            uint32_t ah[2][4], al[2][4], bh[8][2];                                 \
            _Pragma("unroll")                                                      \
            for (int mt = 0; mt < 2; ++mt) {                                       \
                uint32_t ra = sA + (uint32_t)((wm + mt * 16 + (lane & 15)) * GSTR +\
                                              ks + (lane >> 4) * 8) * 2u;          \
                ldsm4(ah[mt], ra);                                                 \
                ldsm4(al[mt], ra + dAl);                                           \
            }                                                                      \
            _Pragma("unroll")                                                      \
            for (int p = 0; p < 4; ++p) {                                          \
                uint32_t rb = sA + dB + (uint32_t)((wn + p * 16 + (lane & 15)) * GSTR + \
                                                   ks + (lane >> 4) * 8) * 2u;     \
                uint32_t t[4];                                                     \
                ldsm4(t, rb);                                                      \
                bh[2 * p][0] = t[0]; bh[2 * p + 1][0] = t[1];                      \
                bh[2 * p][1] = t[2]; bh[2 * p + 1][1] = t[3];                      \
            }                                                                      \
            _Pragma("unroll")                                                      \
            for (int mt = 0; mt < 2; ++mt)                                         \
                _Pragma("unroll")                                                  \
                for (int nt = 0; nt < 8; ++nt) mma16816(acc[mt][nt], ah[mt], bh[nt]); \
            _Pragma("unroll")                                                      \
            for (int mt = 0; mt < 2; ++mt)                                         \
                _Pragma("unroll")                                                  \
                for (int nt = 0; nt < 8; ++nt) mma16816(acc[mt][nt], al[mt], bh[nt]); \
        }                                                                          \
        __syncthreads();                                                           \
    }

// ---------------------------------------------------------------------------
// GEMM1 fused: qkv = x @ W_qkv^T (split-A) with RoPE + layout epilogue.
// ---------------------------------------------------------------------------
__global__ __launch_bounds__(256) void gemm1_fused_kernel(
    const __half* __restrict__ Ah, const __half* __restrict__ Al,
    const __half* __restrict__ Bh,
    const float* __restrict__ ct, const float* __restrict__ st,
    __half* __restrict__ Qh, __half* __restrict__ Ql,
    __half* __restrict__ Kh, __half* __restrict__ Vth)
{
    extern __shared__ __half sm[];
    const uint32_t sbase = smem_u32(sm);
    const int tid  = threadIdx.x;
    const int lane = tid & 31;
    const int wid  = tid >> 5;
    const int bm = blockIdx.y * 128;
    const int bn = blockIdx.x * 128;
    const int wm = (wid & 3) * 32;
    const int wn = (wid >> 2) * 64;

    float acc[2][8][4];
#pragma unroll
    for (int mt = 0; mt < 2; ++mt)
#pragma unroll
        for (int nt = 0; nt < 8; ++nt)
#pragma unroll
            for (int v = 0; v < 4; ++v) acc[mt][nt][v] = 0.f;

    GEMM_MAINLOOP(Ah, Al, Bh, D_)

    // ---- epilogue: acc -> smem fp32 (stride 129) ----
    float* sf = (float*)sm;
#pragma unroll
    for (int mt = 0; mt < 2; ++mt) {
        int row = wm + mt * 16 + (lane >> 2);
#pragma unroll
        for (int nt = 0; nt < 8; ++nt) {
            int col = wn + nt * 8 + (lane & 3) * 2;
            sf[row * 129 + col]           = acc[mt][nt][0];
            sf[row * 129 + col + 1]       = acc[mt][nt][1];
            sf[(row + 8) * 129 + col]     = acc[mt][nt][2];
            sf[(row + 8) * 129 + col + 1] = acc[mt][nt][3];
        }
    }
    __syncthreads();

    const int t    = bn >> 7;
    const int h    = t & 15;
    const int kind = t >> 4;        // 0=q 1=k 2=v
    const int b    = bm >> 11;
    const int s0   = bm & (S_ - 1);

    if (kind < 2) {
        for (int idx = tid; idx < 128 * 64; idx += 256) {
            int r = idx >> 6, d = idx & 63;
            float lo_v = sf[r * 129 + d];
            float hi_v = sf[r * 129 + d + 64];
            int s = s0 + r;
            float c  = ct[(s << 6) + d];
            float sn = st[(s << 6) + d];
            float e0 = lo_v * c - hi_v * sn;
            float e1 = hi_v * c + lo_v * sn;
            size_t dst = ((size_t)(b * H_ + h) * S_ + s) * HD_ + d;
            if (kind == 0) {
                e0 *= 0.08838834764831845f;
                e1 *= 0.08838834764831845f;
                __half h0 = __float2half_rn(e0);
                __half h1 = __float2half_rn(e1);
                Qh[dst]      = h0;
                Qh[dst + 64] = h1;
                Ql[dst]      = __float2half_rn(e0 - __half2float(h0));
                Ql[dst + 64] = __float2half_rn(e1 - __half2float(h1));
            } else {
                Kh[dst]      = __float2half_rn(e0);
                Kh[dst + 64] = __float2half_rn(e1);
            }
        }
    } else {
        __half* vdst = Vth + (size_t)(b * H_ + h) * HD_ * S_;
        for (int idx = tid; idx < 128 * 128; idx += 256) {
            int r = idx & 127, d = idx >> 7;
            vdst[(size_t)d * S_ + s0 + r] = __float2half_rn(sf[r * 129 + d]);
        }
    }
}

// ---------------------------------------------------------------------------
// GEMM2: out = O @ W_o^T — single-A (O rounded), 2-tile stages (73728 B smem)
// ---------------------------------------------------------------------------
__global__ __launch_bounds__(256) void gemm2_mma_kernel(
    const __half* __restrict__ Ah, const __half* __restrict__ Bh,
    float* __restrict__ C, int M, int N, int K)
{
    extern __shared__ __half sm[];
    const uint32_t sbase = smem_u32(sm);
    const int tid  = threadIdx.x;
    const int lane = tid & 31;
    const int wid  = tid >> 5;
    const int bm = blockIdx.y * 128;
    const int bn = blockIdx.x * 128;
    const int wm = (wid & 3) * 32;
    const int wn = (wid >> 2) * 64;

    float acc[2][8][4];
#pragma unroll
    for (int mt = 0; mt < 2; ++mt)
#pragma unroll
        for (int nt = 0; nt < 8; ++nt)
#pragma unroll
            for (int v = 0; v < 4; ++v) acc[mt][nt][v] = 0.f;

    auto load_chunk = [&](int stage, int kc) {
#pragma unroll
        for (int j = 0; j < 8; ++j) {
            int s = tid + j * 256;            // 2048 chunks: A then B
            int tile = s >> 10;
            int r = (s >> 3) & 127;
            int c = s & 7;
            const __half* p = (tile == 0) ? Ah : Bh;
            int rb = (tile == 0) ? bm : bn;
            const __half* src = p + (size_t)(rb + r) * K + kc + c * 8;
            uint32_t dst = sbase + (uint32_t)(stage * STG2_E + tile * TILE_E +
                                              r * GSTR + c * 8) * 2u;
            CP16(dst, src);
        }
    };

    const int NC = K / 64;
    load_chunk(0, 0);
    CP_COMMIT();

    for (int i = 0; i < NC; ++i) {
        if (i + 1 < NC) {
            load_chunk((i + 1) & 1, (i + 1) * 64);
            CP_COMMIT();
            CP_WAIT(1);
        } else {
            CP_WAIT(0);
        }
        __syncthreads();

        const uint32_t sA = sbase + (uint32_t)((i & 1) * STG2_E) * 2u;
        const uint32_t dB = TILE_E * 2u;

#pragma unroll
        for (int ks = 0; ks < 64; ks += 16) {
            uint32_t ah[2][4], bh[8][2];
#pragma unroll
            for (int mt = 0; mt < 2; ++mt) {
                uint32_t ra = sA + (uint32_t)((wm + mt * 16 + (lane & 15)) * GSTR +
                                              ks + (lane >> 4) * 8) * 2u;
                ldsm4(ah[mt], ra);
            }
#pragma unroll
            for (int p = 0; p < 4; ++p) {
                uint32_t rb = sA + dB + (uint32_t)((wn + p * 16 + (lane & 15)) * GSTR +
                                                   ks + (lane >> 4) * 8) * 2u;
                uint32_t t[4];
                ldsm4(t, rb);
                bh[2 * p][0] = t[0]; bh[2 * p + 1][0] = t[1];
                bh[2 * p][1] = t[2]; bh[2 * p + 1][1] = t[3];
            }
#pragma unroll
            for (int mt = 0; mt < 2; ++mt)
#pragma unroll
                for (int nt = 0; nt < 8; ++nt) mma16816(acc[mt][nt], ah[mt], bh[nt]);
        }
        __syncthreads();
    }

#pragma unroll
    for (int mt = 0; mt < 2; ++mt) {
        int row = bm + wm + mt * 16 + (lane >> 2);
#pragma unroll
        for (int nt = 0; nt < 8; ++nt) {
            int col = bn + wn + nt * 8 + (lane & 3) * 2;
            *(float2*)&C[(size_t)row * N + col] =
                make_float2(acc[mt][nt][0], acc[mt][nt][1]);
            *(float2*)&C[(size_t)(row + 8) * N + col] =
                make_float2(acc[mt][nt][2], acc[mt][nt][3]);
        }
    }
}

// ---------------------------------------------------------------------------
// fp32 -> fp16 hi/lo split (x only)
// ---------------------------------------------------------------------------
__global__ void conv_split_kernel(const float* __restrict__ X,
                                  __half* __restrict__ Xh,
                                  __half* __restrict__ Xl, int n4)
{
    int i = blockIdx.x * blockDim.x + threadIdx.x;
    if (i >= n4) return;
    float4 v = *(const float4*)(X + (size_t)i * 4);
    __half2 h01 = __floats2half2_rn(v.x, v.y);
    __half2 h23 = __floats2half2_rn(v.z, v.w);
    float2 f01 = __half22float2(h01);
    float2 f23 = __half22float2(h23);
    __half2 l01 = __floats2half2_rn(v.x - f01.x, v.y - f01.y);
    __half2 l23 = __floats2half2_rn(v.z - f23.x, v.w - f23.y);
    *(__half2*)(Xh + (size_t)i * 4)     = h01;
    *(__half2*)(Xh + (size_t)i * 4 + 2) = h23;
    *(__half2*)(Xl + (size_t)i * 4)     = l01;
    *(__half2*)(Xl + (size_t)i * 4 + 2) = l23;
}

// ---------------------------------------------------------------------------
// fp32 W[R,C] -> transposed fp16 (rounded) T[C,R]
// ---------------------------------------------------------------------------
__global__ __launch_bounds__(256) void conv_tround_kernel(
    const float* __restrict__ W, int R, int C, __half* __restrict__ Th)
{
    __shared__ float t[32][33];
    const int c0 = blockIdx.x * 32, r0 = blockIdx.y * 32;
    const int tx = threadIdx.x & 31, ty = threadIdx.x >> 5;
#pragma unroll
    for (int i = 0; i < 32; i += 8)
        t[ty + i][tx] = W[(size_t)(r0 + ty + i) * C + c0 + tx];
    __syncthreads();
#pragma unroll
    for (int i = 0; i < 32; i += 8)
        Th[(size_t)(c0 + ty + i) * R + r0 + tx] = __float2half_rn(t[tx][ty + i]);
}

// ---------------------------------------------------------------------------
// RoPE table
// ---------------------------------------------------------------------------
__global__ void rope_table_kernel(float* __restrict__ ct, float* __restrict__ st)
{
    int idx = blockIdx.x * blockDim.x + threadIdx.x;
    if (idx >= S_ * 64) return;
    int d = idx & 63;
    int s = idx >> 6;
    float inv_freq = 1.0f / powf(10000.0f, (float)d * (1.0f / 64.0f));
    float ang = (float)s * inv_freq;
    ct[idx] = (float)cos((double)ang);
    st[idx] = (float)sin((double)ang);
}

// ---------------------------------------------------------------------------
// Flash attention: QK split-A (2 MMA), PV rounded-P (1 MMA).
// Q-tile 128, double-buffered KV (64/tile), 256 threads / 8 warps.
// ---------------------------------------------------------------------------
#define QSTR 136
#define VSTR 72
#define QH_OFF 0u
#define QL_OFF 34816u
#define KV_BASE 69632u
#define KV_STG  35840u
#define KH_R 0u
#define VH_R 17408u
#define ATT_SMEM (KV_BASE + 2u * KV_STG)   // 141312 bytes

__global__ __launch_bounds__(256) void attn_mma_kernel(
    const __half* __restrict__ Qh, const __half* __restrict__ Ql,
    const __half* __restrict__ Kh, const __half* __restrict__ Vth,
    __half* __restrict__ Oh)
{
    extern __shared__ char asm_[];
    const uint32_t sb = smem_u32(asm_);
    const int tid  = threadIdx.x;
    const int lane = tid & 31;
    const int wid  = tid >> 5;
    const int qb = (int)(gridDim.x - 1) - (int)blockIdx.x;   // heavy first
    const int h  = blockIdx.y;
    const int b  = blockIdx.z;
    const int bh = b * H_ + h;
    const int q0 = qb * 128;
    const int wq = wid * 16;

    const __half* k_h = Kh + ((size_t)bh * S_) * HD_;
    const __half* v_h = Vth + (size_t)bh * HD_ * S_;

    {
        const __half* q_h = Qh + ((size_t)bh * S_ + q0) * HD_;
        const __half* q_l = Ql + ((size_t)bh * S_ + q0) * HD_;
#pragma unroll
        for (int j = 0; j < 16; ++j) {
            int s = tid + j * 256;
            int hi = s < 2048;
            int u = s & 2047;
            int r = u >> 4, c = u & 15;
            const __half* src = (hi ? q_h : q_l) + (size_t)r * HD_ + c * 8;
            CP16(sb + (hi ? QH_OFF : QL_OFF) + (uint32_t)(r * QSTR + c * 8) * 2u, src);
        }
    }
    CP_COMMIT();

    auto load_kv = [&](int stage, int kv0) {
        const uint32_t st = KV_BASE + (uint32_t)stage * KV_STG;
#pragma unroll
        for (int j = 0; j < 8; ++j) {
            int s = tid + j * 256;
            if (s < 1024) {
                int r = s >> 4, c = s & 15;
                const __half* src = k_h + (size_t)(kv0 + r) * HD_ + c * 8;
                CP16(sb + st + KH_R + (uint32_t)(r * QSTR + c * 8) * 2u, src);
            } else {
                int u = s - 1024;
                int r = u >> 3, c = u & 7;
                const __half* src = v_h + (size_t)r * S_ + kv0 + c * 8;
                CP16(sb + st + VH_R + (uint32_t)(r * VSTR + c * 8) * 2u, src);
            }
        }
    };

    const int nkb = 2 * (qb + 1);
    load_kv(0, 0);
    CP_COMMIT();

    float acc[16][4];
#pragma unroll
    for (int nt = 0; nt < 16; ++nt)
#pragma unroll
        for (int v = 0; v < 4; ++v) acc[nt][v] = 0.f;
    float m0 = -INFINITY, m1 = -INFINITY, l0 = 0.f, l1 = 0.f;

    const int r0 = lane >> 2;
    const int rg0 = q0 + wq + r0;

    for (int kb = 0; kb < nkb; ++kb) {
        const int kv0 = kb * 64;
        __syncthreads();
        if (kb + 1 < nkb) {
            load_kv((kb + 1) & 1, kv0 + 64);
            CP_COMMIT();
            CP_WAIT(1);
        } else {
            CP_WAIT(0);
        }
        __syncthreads();

        const uint32_t skv = sb + KV_BASE + (uint32_t)(kb & 1) * KV_STG;

        float sc[8][4];
#pragma unroll
        for (int nt = 0; nt < 8; ++nt)
#pragma unroll
            for (int v = 0; v < 4; ++v) sc[nt][v] = 0.f;

#pragma unroll
        for (int ks = 0; ks < 8; ++ks) {
            uint32_t a_h[4], a_l[4], b_h[8][2];
            uint32_t ra = sb + QH_OFF + (uint32_t)((wq + (lane & 15)) * QSTR +
                                                   ks * 16 + (lane >> 4) * 8) * 2u;
            ldsm4(a_h, ra);
            ldsm4(a_l, ra + QL_OFF);
#pragma unroll
            for (int p = 0; p < 4; ++p) {
                uint32_t rb = skv + KH_R + (uint32_t)((p * 16 + (lane & 15)) * QSTR +
                                                      ks * 16 + (lane >> 4) * 8) * 2u;
                uint32_t t[4];
                ldsm4(t, rb);
                b_h[2 * p][0] = t[0]; b_h[2 * p + 1][0] = t[1];
                b_h[2 * p][1] = t[2]; b_h[2 * p + 1][1] = t[3];
            }
#pragma unroll
            for (int nt = 0; nt < 8; ++nt) mma16816(sc[nt], a_h, b_h[nt]);
#pragma unroll
            for (int nt = 0; nt < 8; ++nt) mma16816(sc[nt], a_l, b_h[nt]);
        }

        if (kv0 + 63 > q0 + wq) {
#pragma unroll
            for (int nt = 0; nt < 8; ++nt) {
                int c0 = kv0 + nt * 8 + (lane & 3) * 2;
                if (c0     > rg0)     sc[nt][0] = -INFINITY;
                if (c0 + 1 > rg0)     sc[nt][1] = -INFINITY;
                if (c0     > rg0 + 8) sc[nt][2] = -INFINITY;
                if (c0 + 1 > rg0 + 8) sc[nt][3] = -INFINITY;
            }
        }

        float mx0 = -INFINITY, mx1 = -INFINITY;
#pragma unroll
        for (int nt = 0; nt < 8; ++nt) {
            mx0 = fmaxf(mx0, fmaxf(sc[nt][0], sc[nt][1]));
            mx1 = fmaxf(mx1, fmaxf(sc[nt][2], sc[nt][3]));
        }
        mx0 = fmaxf(mx0, __shfl_xor_sync(0xffffffffu, mx0, 1));
        mx0 = fmaxf(mx0, __shfl_xor_sync(0xffffffffu, mx0, 2));
        mx1 = fmaxf(mx1, __shfl_xor_sync(0xffffffffu, mx1, 1));
        mx1 = fmaxf(mx1, __shfl_xor_sync(0xffffffffu, mx1, 2));
        float m0n = fmaxf(m0, mx0), m1n = fmaxf(m1, mx1);
        float al0 = __expf(m0 - m0n), al1 = __expf(m1 - m1n);
        float ps0 = 0.f, ps1 = 0.f;
#pragma unroll
        for (int nt = 0; nt < 8; ++nt) {
            sc[nt][0] = __expf(sc[nt][0] - m0n);
            sc[nt][1] = __expf(sc[nt][1] - m0n);
            sc[nt][2] = __expf(sc[nt][2] - m1n);
            sc[nt][3] = __expf(sc[nt][3] - m1n);
            ps0 += sc[nt][0] + sc[nt][1];
            ps1 += sc[nt][2] + sc[nt][3];
        }
        ps0 += __shfl_xor_sync(0xffffffffu, ps0, 1);
        ps0 += __shfl_xor_sync(0xffffffffu, ps0, 2);
        ps1 += __shfl_xor_sync(0xffffffffu, ps1, 1);
        ps1 += __shfl_xor_sync(0xffffffffu, ps1, 2);
        l0 = l0 * al0 + ps0;
        l1 = l1 * al1 + ps1;
        m0 = m0n; m1 = m1n;
#pragma unroll
        for (int nt = 0; nt < 16; ++nt) {
            acc[nt][0] *= al0; acc[nt][1] *= al0;
            acc[nt][2] *= al1; acc[nt][3] *= al1;
        }

        // ---- pack P (rounded fp16 only) ----
        uint32_t phk[4][4];
#pragma unroll
        for (int kt = 0; kt < 4; ++kt) {
#pragma unroll
            for (int half = 0; half < 2; ++half) {
                int j = 2 * kt + half;
                phk[kt][half * 2 + 0] = pack_h2(sc[j][0], sc[j][1]);
                phk[kt][half * 2 + 1] = pack_h2(sc[j][2], sc[j][3]);
            }
        }

        // ---- O += P @ V (single MMA per fragment) ----
#pragma unroll
        for (int kt = 0; kt < 4; ++kt) {
#pragma unroll
            for (int hlf = 0; hlf < 2; ++hlf) {
                uint32_t bvh[8][2];
#pragma unroll
                for (int p = 0; p < 4; ++p) {
                    uint32_t rb = skv + VH_R +
                        (uint32_t)((hlf * 64 + p * 16 + (lane & 15)) * VSTR +
                                   kt * 16 + (lane >> 4) * 8) * 2u;
                    uint32_t t[4];
                    ldsm4(t, rb);
                    bvh[2 * p][0] = t[0]; bvh[2 * p + 1][0] = t[1];
                    bvh[2 * p][1] = t[2]; bvh[2 * p + 1][1] = t[3];
                }
#pragma unroll
                for (int nt = 0; nt < 8; ++nt) mma16816(acc[hlf * 8 + nt], phk[kt], bvh[nt]);
            }
        }
    }

    // ---- finalize + write O rounded fp16 (GEMM2 A operand) ----
    float inv0 = 1.f / l0, inv1 = 1.f / l1;
    size_t tok0 = (size_t)b * S_ + q0 + wq + r0;
#pragma unroll
    for (int nt = 0; nt < 16; ++nt) {
        int col = h * HD_ + nt * 8 + (lane & 3) * 2;
        *(uint32_t*)&Oh[tok0 * DM_ + col] =
            pack_h2(acc[nt][0] * inv0, acc[nt][1] * inv0);
        *(uint32_t*)&Oh[(tok0 + 8) * DM_ + col] =
            pack_h2(acc[nt][2] * inv1, acc[nt][3] * inv1);
    }
}

// ---------------------------------------------------------------------------
// Launch
// ---------------------------------------------------------------------------
extern "C" void kernel_launch(void* const* d_in, const int* in_sizes, int n_in,
                              void* d_out, int out_size)
{
    (void)in_sizes; (void)n_in; (void)out_size;
    const float* x     = (const float*)d_in[0];
    const float* W_qkv = (const float*)d_in[1];
    const float* W_o   = (const float*)d_in[2];
    float* out = (float*)d_out;

    float *ct, *st;
    __half *Ah, *Al, *Bh, *Woh, *Qh, *Ql, *Kh, *Vth;
    cudaGetSymbolAddress((void**)&ct,   g_cos);
    cudaGetSymbolAddress((void**)&st,   g_sin);
    cudaGetSymbolAddress((void**)&Ah,   g_Ah);
    cudaGetSymbolAddress((void**)&Al,   g_Al);
    cudaGetSymbolAddress((void**)&Bh,   g_Bh);
    cudaGetSymbolAddress((void**)&Woh,  g_Woh);
    cudaGetSymbolAddress((void**)&Qh,   g_Qh);
    cudaGetSymbolAddress((void**)&Ql,   g_Ql);
    cudaGetSymbolAddress((void**)&Kh,   g_Kh);
    cudaGetSymbolAddress((void**)&Vth,  g_Vth);

    cudaFuncSetAttribute(gemm1_fused_kernel,
                         cudaFuncAttributeMaxDynamicSharedMemorySize, GEMM_SMEM);
    cudaFuncSetAttribute(gemm2_mma_kernel,
                         cudaFuncAttributeMaxDynamicSharedMemorySize, GEMM2_SMEM);
    cudaFuncSetAttribute(attn_mma_kernel,
                         cudaFuncAttributeMaxDynamicSharedMemorySize, ATT_SMEM);

    rope_table_kernel<<<(S_ * 64 + 255) / 256, 256>>>(ct, st);

    conv_split_kernel<<<(M_TOK * D_ / 4 + 255) / 256, 256>>>(x, Ah, Al, M_TOK * D_ / 4);
    conv_tround_kernel<<<dim3(QKV_N / 32, D_ / 32), 256>>>(W_qkv, D_, QKV_N, Bh);
    conv_tround_kernel<<<dim3(DM_ / 32, D_ / 32), 256>>>(W_o, DM_, DM_, Woh);

    // fused qkv-projection + RoPE + attention-operand layout
    gemm1_fused_kernel<<<dim3(QKV_N / 128, M_TOK / 128), 256, GEMM_SMEM>>>(
        Ah, Al, Bh, ct, st, Qh, Ql, Kh, Vth);

    // causal flash attention -> writes Oh into g_Ah (GEMM2 operand)
    attn_mma_kernel<<<dim3(S_ / 128, H_, B_), 256, ATT_SMEM>>>(
        Qh, Ql, Kh, Vth, Ah);

    // out = O @ W_o (single-A GEMM)
    gemm2_mma_kernel<<<dim3(DM_ / 128, M_TOK / 128), 256, GEMM2_SMEM>>>(
        Ah, Woh, out, M_TOK, DM_, D_);
}

// round 11
// speedup vs baseline: 1.4102x; 1.2142x over previous
#include <cuda_runtime.h>
#include <cuda_fp16.h>
#include <math.h>
#include <stdint.h>

// Problem constants
#define B_    2
#define S_    2048
#define D_    2048
#define H_    16
#define HD_   128
#define M_TOK (B_ * S_)          // 4096 tokens
#define QKV_N (3 * H_ * HD_)     // 6144
#define DM_   (H_ * HD_)         // 2048

// ---------------------------------------------------------------------------
// Scratch (__device__ globals; no allocation allowed)
// ---------------------------------------------------------------------------
__device__ float g_cos[S_ * (HD_ / 2)];
__device__ float g_sin[S_ * (HD_ / 2)];
__device__ __half g_Ah[(size_t)M_TOK * D_];        // x hi; later O (rounded)
__device__ __half g_Al[(size_t)M_TOK * D_];        // x lo (Q-projection only)
__device__ __half g_Bh[(size_t)QKV_N * D_];        // W_qkv^T rounded [N][K]
__device__ __half g_Woh[(size_t)DM_ * D_];         // W_o^T rounded [N][K]
__device__ __half g_Qh[(size_t)M_TOK * DM_];       // [b,h,s,hd] (pre-scaled)
__device__ __half g_Ql[(size_t)M_TOK * DM_];
__device__ __half g_Kh[(size_t)M_TOK * DM_];       // rounded only
__device__ __half g_Vth[(size_t)M_TOK * DM_];      // [b,h,hd,s] rounded only

// ---------------------------------------------------------------------------
// PTX helpers
// ---------------------------------------------------------------------------
__device__ __forceinline__ uint32_t smem_u32(const void* p) {
    uint32_t a;
    asm("{ .reg .u64 t; cvta.to.shared.u64 t, %1; cvt.u32.u64 %0, t; }"
        : "=r"(a) : "l"(p));
    return a;
}
#define CP16(dst, src) \
    asm volatile("cp.async.cg.shared.global [%0], [%1], 16;" :: "r"(dst), "l"(src) : "memory")
#define CP_COMMIT() asm volatile("cp.async.commit_group;" ::: "memory")
#define CP_WAIT(n)  asm volatile("cp.async.wait_group %0;" :: "n"(n) : "memory")

__device__ __forceinline__ void ldsm4(uint32_t* r, uint32_t addr) {
    asm volatile("ldmatrix.sync.aligned.m8n8.x4.shared.b16 {%0,%1,%2,%3}, [%4];"
                 : "=r"(r[0]), "=r"(r[1]), "=r"(r[2]), "=r"(r[3]) : "r"(addr));
}
__device__ __forceinline__ void mma16816(float* c, const uint32_t* a, const uint32_t* b) {
    asm volatile(
        "mma.sync.aligned.m16n8k16.row.col.f32.f16.f16.f32 "
        "{%0,%1,%2,%3}, {%4,%5,%6,%7}, {%8,%9}, {%0,%1,%2,%3};"
        : "+f"(c[0]), "+f"(c[1]), "+f"(c[2]), "+f"(c[3])
        : "r"(a[0]), "r"(a[1]), "r"(a[2]), "r"(a[3]), "r"(b[0]), "r"(b[1]));
}
__device__ __forceinline__ uint32_t pack_h2(float x, float y) {
    __half2 t = __floats2half2_rn(x, y);
    return *(uint32_t*)&t;
}

// ---------------------------------------------------------------------------
// GEMM tiling constants
// ---------------------------------------------------------------------------
#define GSTR  72
#define TILE_E (128 * GSTR)
#define STG_E  (3 * TILE_E)
#define GEMM_SMEM (2 * STG_E * 2)        // 110592 B (split-A: Ah,Al,Bh)
#define STG2_E (2 * TILE_E)
#define GEMM2_SMEM (2 * STG2_E * 2)      // 73728 B  (single-A: Ah,Bh)

// Split-A mainloop (Ah+Al vs Bh)
#define GEMM_MAINLOOP(Ah, Al, Bh, KDIM)                                            \
    auto load_chunk = [&](int stage, int kc) {                                     \
        _Pragma("unroll")                                                          \
        for (int j = 0; j < 12; ++j) {                                             \
            int s = tid + j * 256;                                                 \
            int tile = s >> 10;                                                    \
            int r = (s >> 3) & 127;                                                \
            int c = s & 7;                                                         \
            const __half* p = (tile == 0) ? Ah : (tile == 1) ? Al : Bh;            \
            int rb = (tile < 2) ? bm : bn;                                         \
            const __half* src = p + (size_t)(rb + r) * (KDIM) + kc + c * 8;        \
            uint32_t dst = sbase + (uint32_t)(stage * STG_E + tile * TILE_E +      \
                                              r * GSTR + c * 8) * 2u;              \
            CP16(dst, src);                                                        \
        }                                                                          \
    };                                                                             \
    const int NC = (KDIM) / 64;                                                    \
    load_chunk(0, 0);                                                              \
    CP_COMMIT();                                                                   \
    for (int i = 0; i < NC; ++i) {                                                 \
        if (i + 1 < NC) {                                                          \
            load_chunk((i + 1) & 1, (i + 1) * 64);                                 \
            CP_COMMIT();                                                           \
            CP_WAIT(1);                                                            \
        } else {                                                                   \
            CP_WAIT(0);                                                            \
        }                                                                          \
        __syncthreads();                                                           \
        const uint32_t sA  = sbase + (uint32_t)((i & 1) * STG_E) * 2u;             \
        const uint32_t dAl = TILE_E * 2u;                                          \
        const uint32_t dB  = 2u * TILE_E * 2u;                                     \
        _Pragma("unroll")                                                          \
        for (int ks = 0; ks < 64; ks += 16) {                                      \
            uint32_t ah[2][4], al[2][4], bh[8][2];                                 \
            _Pragma("unroll")                                                      \
            for (int mt = 0; mt < 2; ++mt) {                                       \
                uint32_t ra = sA + (uint32_t)((wm + mt * 16 + (lane & 15)) * GSTR +\
                                              ks + (lane >> 4) * 8) * 2u;          \
                ldsm4(ah[mt], ra);                                                 \
                ldsm4(al[mt], ra + dAl);                                           \
            }                                                                      \
            _Pragma("unroll")                                                      \
            for (int p = 0; p < 4; ++p) {                                          \
                uint32_t rb = sA + dB + (uint32_t)((wn + p * 16 + (lane & 15)) * GSTR + \
                                                   ks + (lane >> 4) * 8) * 2u;     \
                uint32_t t[4];                                                     \
                ldsm4(t, rb);                                                      \
                bh[2 * p][0] = t[0]; bh[2 * p + 1][0] = t[1];                      \
                bh[2 * p][1] = t[2]; bh[2 * p + 1][1] = t[3];                      \
            }                                                                      \
            _Pragma("unroll")                                                      \
            for (int mt = 0; mt < 2; ++mt)                                         \
                _Pragma("unroll")                                                  \
                for (int nt = 0; nt < 8; ++nt) mma16816(acc[mt][nt], ah[mt], bh[nt]); \
            _Pragma("unroll")                                                      \
            for (int mt = 0; mt < 2; ++mt)                                         \
                _Pragma("unroll")                                                  \
                for (int nt = 0; nt < 8; ++nt) mma16816(acc[mt][nt], al[mt], bh[nt]); \
        }                                                                          \
        __syncthreads();                                                           \
    }

// Single-A mainloop (Ah vs Bh), 2-tile stages
#define GEMM1A_MAINLOOP(Ah, Bh, KDIM)                                              \
    auto load_chunk = [&](int stage, int kc) {                                     \
        _Pragma("unroll")                                                          \
        for (int j = 0; j < 8; ++j) {                                              \
            int s = tid + j * 256;                                                 \
            int tile = s >> 10;                                                    \
            int r = (s >> 3) & 127;                                                \
            int c = s & 7;                                                         \
            const __half* p = (tile == 0) ? Ah : Bh;                               \
            int rb = (tile == 0) ? bm : bn;                                        \
            const __half* src = p + (size_t)(rb + r) * (KDIM) + kc + c * 8;        \
            uint32_t dst = sbase + (uint32_t)(stage * STG2_E + tile * TILE_E +     \
                                              r * GSTR + c * 8) * 2u;              \
            CP16(dst, src);                                                        \
        }                                                                          \
    };                                                                             \
    const int NC = (KDIM) / 64;                                                    \
    load_chunk(0, 0);                                                              \
    CP_COMMIT();                                                                   \
    for (int i = 0; i < NC; ++i) {                                                 \
        if (i + 1 < NC) {                                                          \
            load_chunk((i + 1) & 1, (i + 1) * 64);                                 \
            CP_COMMIT();                                                           \
            CP_WAIT(1);                                                            \
        } else {                                                                   \
            CP_WAIT(0);                                                            \
        }                                                                          \
        __syncthreads();                                                           \
        const uint32_t sA = sbase + (uint32_t)((i & 1) * STG2_E) * 2u;             \
        const uint32_t dB = TILE_E * 2u;                                           \
        _Pragma("unroll")                                                          \
        for (int ks = 0; ks < 64; ks += 16) {                                      \
            uint32_t ah[2][4], bh[8][2];                                           \
            _Pragma("unroll")                                                      \
            for (int mt = 0; mt < 2; ++mt) {                                       \
                uint32_t ra = sA + (uint32_t)((wm + mt * 16 + (lane & 15)) * GSTR +\
                                              ks + (lane >> 4) * 8) * 2u;          \
                ldsm4(ah[mt], ra);                                                 \
            }                                                                      \
            _Pragma("unroll")                                                      \
            for (int p = 0; p < 4; ++p) {                                          \
                uint32_t rb = sA + dB + (uint32_t)((wn + p * 16 + (lane & 15)) * GSTR + \
                                                   ks + (lane >> 4) * 8) * 2u;     \
                uint32_t t[4];                                                     \
                ldsm4(t, rb);                                                      \
                bh[2 * p][0] = t[0]; bh[2 * p + 1][0] = t[1];                      \
                bh[2 * p][1] = t[2]; bh[2 * p + 1][1] = t[3];                      \
            }                                                                      \
            _Pragma("unroll")                                                      \
            for (int mt = 0; mt < 2; ++mt)                                         \
                _Pragma("unroll")                                                  \
                for (int nt = 0; nt < 8; ++nt) mma16816(acc[mt][nt], ah[mt], bh[nt]); \
        }                                                                          \
        __syncthreads();                                                           \
    }

// ---------------------------------------------------------------------------
// GEMM1-Q: q = x @ Wq^T (split-A) + RoPE + scale + hi/lo split epilogue.
// grid (16 heads, 32 m-tiles)
// ---------------------------------------------------------------------------
__global__ __launch_bounds__(256) void gemm1_q_kernel(
    const __half* __restrict__ Ah, const __half* __restrict__ Al,
    const __half* __restrict__ Bh,
    const float* __restrict__ ct, const float* __restrict__ st,
    __half* __restrict__ Qh, __half* __restrict__ Ql)
{
    extern __shared__ __half sm[];
    const uint32_t sbase = smem_u32(sm);
    const int tid  = threadIdx.x;
    const int lane = tid & 31;
    const int wid  = tid >> 5;
    const int bm = blockIdx.y * 128;
    const int bn = blockIdx.x * 128;          // q region of W_qkv^T
    const int wm = (wid & 3) * 32;
    const int wn = (wid >> 2) * 64;

    float acc[2][8][4];
#pragma unroll
    for (int mt = 0; mt < 2; ++mt)
#pragma unroll
        for (int nt = 0; nt < 8; ++nt)
#pragma unroll
            for (int v = 0; v < 4; ++v) acc[mt][nt][v] = 0.f;

    GEMM_MAINLOOP(Ah, Al, Bh, D_)

    float* sf = (float*)sm;
#pragma unroll
    for (int mt = 0; mt < 2; ++mt) {
        int row = wm + mt * 16 + (lane >> 2);
#pragma unroll
        for (int nt = 0; nt < 8; ++nt) {
            int col = wn + nt * 8 + (lane & 3) * 2;
            sf[row * 129 + col]           = acc[mt][nt][0];
            sf[row * 129 + col + 1]       = acc[mt][nt][1];
            sf[(row + 8) * 129 + col]     = acc[mt][nt][2];
            sf[(row + 8) * 129 + col + 1] = acc[mt][nt][3];
        }
    }
    __syncthreads();

    const int h  = blockIdx.x;
    const int b  = bm >> 11;
    const int s0 = bm & (S_ - 1);

    for (int idx = tid; idx < 128 * 64; idx += 256) {
        int r = idx >> 6, d = idx & 63;
        float lo_v = sf[r * 129 + d];
        float hi_v = sf[r * 129 + d + 64];
        int s = s0 + r;
        float c  = ct[(s << 6) + d];
        float sn = st[(s << 6) + d];
        float e0 = (lo_v * c - hi_v * sn) * 0.08838834764831845f;
        float e1 = (hi_v * c + lo_v * sn) * 0.08838834764831845f;
        size_t dst = ((size_t)(b * H_ + h) * S_ + s) * HD_ + d;
        __half h0 = __float2half_rn(e0);
        __half h1 = __float2half_rn(e1);
        Qh[dst]      = h0;
        Qh[dst + 64] = h1;
        Ql[dst]      = __float2half_rn(e0 - __half2float(h0));
        Ql[dst + 64] = __float2half_rn(e1 - __half2float(h1));
    }
}

// ---------------------------------------------------------------------------
// GEMM1-KV: k,v = x @ Wkv^T (single-A; outputs are fp16-rounded anyway)
// grid (32, 32): x = kind*16 + head. K: RoPE+round. V: transpose+round.
// ---------------------------------------------------------------------------
__global__ __launch_bounds__(256) void gemm1_kv_kernel(
    const __half* __restrict__ Ah, const __half* __restrict__ Bh,
    const float* __restrict__ ct, const float* __restrict__ st,
    __half* __restrict__ Kh, __half* __restrict__ Vth)
{
    extern __shared__ __half sm[];
    const uint32_t sbase = smem_u32(sm);
    const int tid  = threadIdx.x;
    const int lane = tid & 31;
    const int wid  = tid >> 5;
    const int bm = blockIdx.y * 128;
    const int bn = DM_ + blockIdx.x * 128;    // k/v region of W_qkv^T
    const int wm = (wid & 3) * 32;
    const int wn = (wid >> 2) * 64;

    float acc[2][8][4];
#pragma unroll
    for (int mt = 0; mt < 2; ++mt)
#pragma unroll
        for (int nt = 0; nt < 8; ++nt)
#pragma unroll
            for (int v = 0; v < 4; ++v) acc[mt][nt][v] = 0.f;

    GEMM1A_MAINLOOP(Ah, Bh, D_)

    float* sf = (float*)sm;
#pragma unroll
    for (int mt = 0; mt < 2; ++mt) {
        int row = wm + mt * 16 + (lane >> 2);
#pragma unroll
        for (int nt = 0; nt < 8; ++nt) {
            int col = wn + nt * 8 + (lane & 3) * 2;
            sf[row * 129 + col]           = acc[mt][nt][0];
            sf[row * 129 + col + 1]       = acc[mt][nt][1];
            sf[(row + 8) * 129 + col]     = acc[mt][nt][2];
            sf[(row + 8) * 129 + col + 1] = acc[mt][nt][3];
        }
    }
    __syncthreads();

    const int kind = blockIdx.x >> 4;   // 0=k 1=v
    const int h    = blockIdx.x & 15;
    const int b    = bm >> 11;
    const int s0   = bm & (S_ - 1);

    if (kind == 0) {
        for (int idx = tid; idx < 128 * 64; idx += 256) {
            int r = idx >> 6, d = idx & 63;
            float lo_v = sf[r * 129 + d];
            float hi_v = sf[r * 129 + d + 64];
            int s = s0 + r;
            float c  = ct[(s << 6) + d];
            float sn = st[(s << 6) + d];
            size_t dst = ((size_t)(b * H_ + h) * S_ + s) * HD_ + d;
            Kh[dst]      = __float2half_rn(lo_v * c - hi_v * sn);
            Kh[dst + 64] = __float2half_rn(hi_v * c + lo_v * sn);
        }
    } else {
        __half* vdst = Vth + (size_t)(b * H_ + h) * HD_ * S_;
        for (int idx = tid; idx < 128 * 128; idx += 256) {
            int r = idx & 127, d = idx >> 7;
            vdst[(size_t)d * S_ + s0 + r] = __float2half_rn(sf[r * 129 + d]);
        }
    }
}

// ---------------------------------------------------------------------------
// GEMM2: out = O @ W_o^T — single-A (O rounded)
// ---------------------------------------------------------------------------
__global__ __launch_bounds__(256) void gemm2_mma_kernel(
    const __half* __restrict__ Ah, const __half* __restrict__ Bh,
    float* __restrict__ C, int M, int N, int K)
{
    extern __shared__ __half sm[];
    const uint32_t sbase = smem_u32(sm);
    const int tid  = threadIdx.x;
    const int lane = tid & 31;
    const int wid  = tid >> 5;
    const int bm = blockIdx.y * 128;
    const int bn = blockIdx.x * 128;
    const int wm = (wid & 3) * 32;
    const int wn = (wid >> 2) * 64;

    float acc[2][8][4];
#pragma unroll
    for (int mt = 0; mt < 2; ++mt)
#pragma unroll
        for (int nt = 0; nt < 8; ++nt)
#pragma unroll
            for (int v = 0; v < 4; ++v) acc[mt][nt][v] = 0.f;

    GEMM1A_MAINLOOP(Ah, Bh, K)

#pragma unroll
    for (int mt = 0; mt < 2; ++mt) {
        int row = bm + wm + mt * 16 + (lane >> 2);
#pragma unroll
        for (int nt = 0; nt < 8; ++nt) {
            int col = bn + wn + nt * 8 + (lane & 3) * 2;
            *(float2*)&C[(size_t)row * N + col] =
                make_float2(acc[mt][nt][0], acc[mt][nt][1]);
            *(float2*)&C[(size_t)(row + 8) * N + col] =
                make_float2(acc[mt][nt][2], acc[mt][nt][3]);
        }
    }
}

// ---------------------------------------------------------------------------
// fp32 -> fp16 hi/lo split (x only)
// ---------------------------------------------------------------------------
__global__ void conv_split_kernel(const float* __restrict__ X,
                                  __half* __restrict__ Xh,
                                  __half* __restrict__ Xl, int n4)
{
    int i = blockIdx.x * blockDim.x + threadIdx.x;
    if (i >= n4) return;
    float4 v = *(const float4*)(X + (size_t)i * 4);
    __half2 h01 = __floats2half2_rn(v.x, v.y);
    __half2 h23 = __floats2half2_rn(v.z, v.w);
    float2 f01 = __half22float2(h01);
    float2 f23 = __half22float2(h23);
    __half2 l01 = __floats2half2_rn(v.x - f01.x, v.y - f01.y);
    __half2 l23 = __floats2half2_rn(v.z - f23.x, v.w - f23.y);
    *(__half2*)(Xh + (size_t)i * 4)     = h01;
    *(__half2*)(Xh + (size_t)i * 4 + 2) = h23;
    *(__half2*)(Xl + (size_t)i * 4)     = l01;
    *(__half2*)(Xl + (size_t)i * 4 + 2) = l23;
}

// ---------------------------------------------------------------------------
// fp32 W[R,C] -> transposed fp16 (rounded) T[C,R]
// ---------------------------------------------------------------------------
__global__ __launch_bounds__(256) void conv_tround_kernel(
    const float* __restrict__ W, int R, int C, __half* __restrict__ Th)
{
    __shared__ float t[32][33];
    const int c0 = blockIdx.x * 32, r0 = blockIdx.y * 32;
    const int tx = threadIdx.x & 31, ty = threadIdx.x >> 5;
#pragma unroll
    for (int i = 0; i < 32; i += 8)
        t[ty + i][tx] = W[(size_t)(r0 + ty + i) * C + c0 + tx];
    __syncthreads();
#pragma unroll
    for (int i = 0; i < 32; i += 8)
        Th[(size_t)(c0 + ty + i) * R + r0 + tx] = __float2half_rn(t[tx][ty + i]);
}

// ---------------------------------------------------------------------------
// RoPE table
// ---------------------------------------------------------------------------
__global__ void rope_table_kernel(float* __restrict__ ct, float* __restrict__ st)
{
    int idx = blockIdx.x * blockDim.x + threadIdx.x;
    if (idx >= S_ * 64) return;
    int d = idx & 63;
    int s = idx >> 6;
    float inv_freq = 1.0f / powf(10000.0f, (float)d * (1.0f / 64.0f));
    float ang = (float)s * inv_freq;
    ct[idx] = (float)cos((double)ang);
    st[idx] = (float)sin((double)ang);
}

// ---------------------------------------------------------------------------
// Flash attention: QK split-A (2 MMA), PV rounded-P (1 MMA).
// ---------------------------------------------------------------------------
#define QSTR 136
#define VSTR 72
#define QH_OFF 0u
#define QL_OFF 34816u
#define KV_BASE 69632u
#define KV_STG  35840u
#define KH_R 0u
#define VH_R 17408u
#define ATT_SMEM (KV_BASE + 2u * KV_STG)   // 141312 bytes

__global__ __launch_bounds__(256) void attn_mma_kernel(
    const __half* __restrict__ Qh, const __half* __restrict__ Ql,
    const __half* __restrict__ Kh, const __half* __restrict__ Vth,
    __half* __restrict__ Oh)
{
    extern __shared__ char asm_[];
    const uint32_t sb = smem_u32(asm_);
    const int tid  = threadIdx.x;
    const int lane = tid & 31;
    const int wid  = tid >> 5;
    const int qb = (int)(gridDim.x - 1) - (int)blockIdx.x;   // heavy first
    const int h  = blockIdx.y;
    const int b  = blockIdx.z;
    const int bh = b * H_ + h;
    const int q0 = qb * 128;
    const int wq = wid * 16;

    const __half* k_h = Kh + ((size_t)bh * S_) * HD_;
    const __half* v_h = Vth + (size_t)bh * HD_ * S_;

    {
        const __half* q_h = Qh + ((size_t)bh * S_ + q0) * HD_;
        const __half* q_l = Ql + ((size_t)bh * S_ + q0) * HD_;
#pragma unroll
        for (int j = 0; j < 16; ++j) {
            int s = tid + j * 256;
            int hi = s < 2048;
            int u = s & 2047;
            int r = u >> 4, c = u & 15;
            const __half* src = (hi ? q_h : q_l) + (size_t)r * HD_ + c * 8;
            CP16(sb + (hi ? QH_OFF : QL_OFF) + (uint32_t)(r * QSTR + c * 8) * 2u, src);
        }
    }
    CP_COMMIT();

    auto load_kv = [&](int stage, int kv0) {
        const uint32_t st = KV_BASE + (uint32_t)stage * KV_STG;
#pragma unroll
        for (int j = 0; j < 8; ++j) {
            int s = tid + j * 256;
            if (s < 1024) {
                int r = s >> 4, c = s & 15;
                const __half* src = k_h + (size_t)(kv0 + r) * HD_ + c * 8;
                CP16(sb + st + KH_R + (uint32_t)(r * QSTR + c * 8) * 2u, src);
            } else {
                int u = s - 1024;
                int r = u >> 3, c = u & 7;
                const __half* src = v_h + (size_t)r * S_ + kv0 + c * 8;
                CP16(sb + st + VH_R + (uint32_t)(r * VSTR + c * 8) * 2u, src);
            }
        }
    };

    const int nkb = 2 * (qb + 1);
    load_kv(0, 0);
    CP_COMMIT();

    float acc[16][4];
#pragma unroll
    for (int nt = 0; nt < 16; ++nt)
#pragma unroll
        for (int v = 0; v < 4; ++v) acc[nt][v] = 0.f;
    float m0 = -INFINITY, m1 = -INFINITY, l0 = 0.f, l1 = 0.f;

    const int r0 = lane >> 2;
    const int rg0 = q0 + wq + r0;

    for (int kb = 0; kb < nkb; ++kb) {
        const int kv0 = kb * 64;
        __syncthreads();
        if (kb + 1 < nkb) {
            load_kv((kb + 1) & 1, kv0 + 64);
            CP_COMMIT();
            CP_WAIT(1);
        } else {
            CP_WAIT(0);
        }
        __syncthreads();

        const uint32_t skv = sb + KV_BASE + (uint32_t)(kb & 1) * KV_STG;

        float sc[8][4];
#pragma unroll
        for (int nt = 0; nt < 8; ++nt)
#pragma unroll
            for (int v = 0; v < 4; ++v) sc[nt][v] = 0.f;

#pragma unroll
        for (int ks = 0; ks < 8; ++ks) {
            uint32_t a_h[4], a_l[4], b_h[8][2];
            uint32_t ra = sb + QH_OFF + (uint32_t)((wq + (lane & 15)) * QSTR +
                                                   ks * 16 + (lane >> 4) * 8) * 2u;
            ldsm4(a_h, ra);
            ldsm4(a_l, ra + QL_OFF);
#pragma unroll
            for (int p = 0; p < 4; ++p) {
                uint32_t rb = skv + KH_R + (uint32_t)((p * 16 + (lane & 15)) * QSTR +
                                                      ks * 16 + (lane >> 4) * 8) * 2u;
                uint32_t t[4];
                ldsm4(t, rb);
                b_h[2 * p][0] = t[0]; b_h[2 * p + 1][0] = t[1];
                b_h[2 * p][1] = t[2]; b_h[2 * p + 1][1] = t[3];
            }
#pragma unroll
            for (int nt = 0; nt < 8; ++nt) mma16816(sc[nt], a_h, b_h[nt]);
#pragma unroll
            for (int nt = 0; nt < 8; ++nt) mma16816(sc[nt], a_l, b_h[nt]);
        }

        if (kv0 + 63 > q0 + wq) {
#pragma unroll
            for (int nt = 0; nt < 8; ++nt) {
                int c0 = kv0 + nt * 8 + (lane & 3) * 2;
                if (c0     > rg0)     sc[nt][0] = -INFINITY;
                if (c0 + 1 > rg0)     sc[nt][1] = -INFINITY;
                if (c0     > rg0 + 8) sc[nt][2] = -INFINITY;
                if (c0 + 1 > rg0 + 8) sc[nt][3] = -INFINITY;
            }
        }

        float mx0 = -INFINITY, mx1 = -INFINITY;
#pragma unroll
        for (int nt = 0; nt < 8; ++nt) {
            mx0 = fmaxf(mx0, fmaxf(sc[nt][0], sc[nt][1]));
            mx1 = fmaxf(mx1, fmaxf(sc[nt][2], sc[nt][3]));
        }
        mx0 = fmaxf(mx0, __shfl_xor_sync(0xffffffffu, mx0, 1));
        mx0 = fmaxf(mx0, __shfl_xor_sync(0xffffffffu, mx0, 2));
        mx1 = fmaxf(mx1, __shfl_xor_sync(0xffffffffu, mx1, 1));
        mx1 = fmaxf(mx1, __shfl_xor_sync(0xffffffffu, mx1, 2));
        float m0n = fmaxf(m0, mx0), m1n = fmaxf(m1, mx1);
        float al0 = __expf(m0 - m0n), al1 = __expf(m1 - m1n);
        float ps0 = 0.f, ps1 = 0.f;
#pragma unroll
        for (int nt = 0; nt < 8; ++nt) {
            sc[nt][0] = __expf(sc[nt][0] - m0n);
            sc[nt][1] = __expf(sc[nt][1] - m0n);
            sc[nt][2] = __expf(sc[nt][2] - m1n);
            sc[nt][3] = __expf(sc[nt][3] - m1n);
            ps0 += sc[nt][0] + sc[nt][1];
            ps1 += sc[nt][2] + sc[nt][3];
        }
        ps0 += __shfl_xor_sync(0xffffffffu, ps0, 1);
        ps0 += __shfl_xor_sync(0xffffffffu, ps0, 2);
        ps1 += __shfl_xor_sync(0xffffffffu, ps1, 1);
        ps1 += __shfl_xor_sync(0xffffffffu, ps1, 2);
        l0 = l0 * al0 + ps0;
        l1 = l1 * al1 + ps1;
        m0 = m0n; m1 = m1n;
#pragma unroll
        for (int nt = 0; nt < 16; ++nt) {
            acc[nt][0] *= al0; acc[nt][1] *= al0;
            acc[nt][2] *= al1; acc[nt][3] *= al1;
        }

        uint32_t phk[4][4];
#pragma unroll
        for (int kt = 0; kt < 4; ++kt) {
#pragma unroll
            for (int half = 0; half < 2; ++half) {
                int j = 2 * kt + half;
                phk[kt][half * 2 + 0] = pack_h2(sc[j][0], sc[j][1]);
                phk[kt][half * 2 + 1] = pack_h2(sc[j][2], sc[j][3]);
            }
        }

#pragma unroll
        for (int kt = 0; kt < 4; ++kt) {
#pragma unroll
            for (int hlf = 0; hlf < 2; ++hlf) {
                uint32_t bvh[8][2];
#pragma unroll
                for (int p = 0; p < 4; ++p) {
                    uint32_t rb = skv + VH_R +
                        (uint32_t)((hlf * 64 + p * 16 + (lane & 15)) * VSTR +
                                   kt * 16 + (lane >> 4) * 8) * 2u;
                    uint32_t t[4];
                    ldsm4(t, rb);
                    bvh[2 * p][0] = t[0]; bvh[2 * p + 1][0] = t[1];
                    bvh[2 * p][1] = t[2]; bvh[2 * p + 1][1] = t[3];
                }
#pragma unroll
                for (int nt = 0; nt < 8; ++nt) mma16816(acc[hlf * 8 + nt], phk[kt], bvh[nt]);
            }
        }
    }

    float inv0 = 1.f / l0, inv1 = 1.f / l1;
    size_t tok0 = (size_t)b * S_ + q0 + wq + r0;
#pragma unroll
    for (int nt = 0; nt < 16; ++nt) {
        int col = h * HD_ + nt * 8 + (lane & 3) * 2;
        *(uint32_t*)&Oh[tok0 * DM_ + col] =
            pack_h2(acc[nt][0] * inv0, acc[nt][1] * inv0);
        *(uint32_t*)&Oh[(tok0 + 8) * DM_ + col] =
            pack_h2(acc[nt][2] * inv1, acc[nt][3] * inv1);
    }
}

// ---------------------------------------------------------------------------
// Launch
// ---------------------------------------------------------------------------
extern "C" void kernel_launch(void* const* d_in, const int* in_sizes, int n_in,
                              void* d_out, int out_size)
{
    (void)in_sizes; (void)n_in; (void)out_size;
    const float* x     = (const float*)d_in[0];
    const float* W_qkv = (const float*)d_in[1];
    const float* W_o   = (const float*)d_in[2];
    float* out = (float*)d_out;

    float *ct, *st;
    __half *Ah, *Al, *Bh, *Woh, *Qh, *Ql, *Kh, *Vth;
    cudaGetSymbolAddress((void**)&ct,   g_cos);
    cudaGetSymbolAddress((void**)&st,   g_sin);
    cudaGetSymbolAddress((void**)&Ah,   g_Ah);
    cudaGetSymbolAddress((void**)&Al,   g_Al);
    cudaGetSymbolAddress((void**)&Bh,   g_Bh);
    cudaGetSymbolAddress((void**)&Woh,  g_Woh);
    cudaGetSymbolAddress((void**)&Qh,   g_Qh);
    cudaGetSymbolAddress((void**)&Ql,   g_Ql);
    cudaGetSymbolAddress((void**)&Kh,   g_Kh);
    cudaGetSymbolAddress((void**)&Vth,  g_Vth);

    cudaFuncSetAttribute(gemm1_q_kernel,
                         cudaFuncAttributeMaxDynamicSharedMemorySize, GEMM_SMEM);
    cudaFuncSetAttribute(gemm1_kv_kernel,
                         cudaFuncAttributeMaxDynamicSharedMemorySize, GEMM2_SMEM);
    cudaFuncSetAttribute(gemm2_mma_kernel,
                         cudaFuncAttributeMaxDynamicSharedMemorySize, GEMM2_SMEM);
    cudaFuncSetAttribute(attn_mma_kernel,
                         cudaFuncAttributeMaxDynamicSharedMemorySize, ATT_SMEM);

    rope_table_kernel<<<(S_ * 64 + 255) / 256, 256>>>(ct, st);

    conv_split_kernel<<<(M_TOK * D_ / 4 + 255) / 256, 256>>>(x, Ah, Al, M_TOK * D_ / 4);
    conv_tround_kernel<<<dim3(QKV_N / 32, D_ / 32), 256>>>(W_qkv, D_, QKV_N, Bh);
    conv_tround_kernel<<<dim3(DM_ / 32, D_ / 32), 256>>>(W_o, DM_, DM_, Woh);

    // q projection (split-A, error-compensated) + RoPE epilogue
    gemm1_q_kernel<<<dim3(H_, M_TOK / 128), 256, GEMM_SMEM>>>(
        Ah, Al, Bh, ct, st, Qh, Ql);

    // k,v projection (single-A; outputs rounded anyway) + RoPE/transpose
    gemm1_kv_kernel<<<dim3(2 * H_, M_TOK / 128), 256, GEMM2_SMEM>>>(
        Ah, Bh, ct, st, Kh, Vth);

    // causal flash attention -> writes Oh into g_Ah (GEMM2 operand)
    attn_mma_kernel<<<dim3(S_ / 128, H_, B_), 256, ATT_SMEM>>>(
        Qh, Ql, Kh, Vth, Ah);

    // out = O @ W_o (single-A GEMM)
    gemm2_mma_kernel<<<dim3(DM_ / 128, M_TOK / 128), 256, GEMM2_SMEM>>>(
        Ah, Woh, out, M_TOK, DM_, D_);
}

// round 12
// speedup vs baseline: 1.4134x; 1.0023x over previous
#include <cuda_runtime.h>
#include <cuda_fp16.h>
#include <math.h>
#include <stdint.h>

// Problem constants
#define B_    2
#define S_    2048
#define D_    2048
#define H_    16
#define HD_   128
#define M_TOK (B_ * S_)          // 4096 tokens
#define QKV_N (3 * H_ * HD_)     // 6144
#define DM_   (H_ * HD_)         // 2048

// ---------------------------------------------------------------------------
// Scratch (__device__ globals; no allocation allowed)
// ---------------------------------------------------------------------------
__device__ float g_cos[S_ * (HD_ / 2)];
__device__ float g_sin[S_ * (HD_ / 2)];
__device__ __half g_Ah[(size_t)M_TOK * D_];        // x hi; later O (rounded)
__device__ __half g_Al[(size_t)M_TOK * D_];        // x lo (Q-projection only)
__device__ __half g_Bh[(size_t)QKV_N * D_];        // W_qkv^T rounded [N][K]
__device__ __half g_Woh[(size_t)DM_ * D_];         // W_o^T rounded [N][K]
__device__ __half g_Qh[(size_t)M_TOK * DM_];       // [b,h,s,hd] (pre-scaled)
__device__ __half g_Ql[(size_t)M_TOK * DM_];
__device__ __half g_Kh[(size_t)M_TOK * DM_];       // rounded only
__device__ __half g_Vth[(size_t)M_TOK * DM_];      // [b,h,hd,s] rounded only

// ---------------------------------------------------------------------------
// PTX helpers
// ---------------------------------------------------------------------------
__device__ __forceinline__ uint32_t smem_u32(const void* p) {
    uint32_t a;
    asm("{ .reg .u64 t; cvta.to.shared.u64 t, %1; cvt.u32.u64 %0, t; }"
        : "=r"(a) : "l"(p));
    return a;
}
#define CP16(dst, src) \
    asm volatile("cp.async.cg.shared.global [%0], [%1], 16;" :: "r"(dst), "l"(src) : "memory")
#define CP_COMMIT() asm volatile("cp.async.commit_group;" ::: "memory")
#define CP_WAIT(n)  asm volatile("cp.async.wait_group %0;" :: "n"(n) : "memory")

__device__ __forceinline__ void ldsm4(uint32_t* r, uint32_t addr) {
    asm volatile("ldmatrix.sync.aligned.m8n8.x4.shared.b16 {%0,%1,%2,%3}, [%4];"
                 : "=r"(r[0]), "=r"(r[1]), "=r"(r[2]), "=r"(r[3]) : "r"(addr));
}
__device__ __forceinline__ void mma16816(float* c, const uint32_t* a, const uint32_t* b) {
    asm volatile(
        "mma.sync.aligned.m16n8k16.row.col.f32.f16.f16.f32 "
        "{%0,%1,%2,%3}, {%4,%5,%6,%7}, {%8,%9}, {%0,%1,%2,%3};"
        : "+f"(c[0]), "+f"(c[1]), "+f"(c[2]), "+f"(c[3])
        : "r"(a[0]), "r"(a[1]), "r"(a[2]), "r"(a[3]), "r"(b[0]), "r"(b[1]));
}
__device__ __forceinline__ uint32_t pack_h2(float x, float y) {
    __half2 t = __floats2half2_rn(x, y);
    return *(uint32_t*)&t;
}

// ---------------------------------------------------------------------------
// GEMM tiling constants
// ---------------------------------------------------------------------------
#define GSTR  72
#define TILE_E (128 * GSTR)
#define STG_E  (3 * TILE_E)
#define GEMM_SMEM (2 * STG_E * 2)        // 110592 B (split-A: Ah,Al,Bh)
#define STG2_E (2 * TILE_E)
#define GEMM2_SMEM (2 * STG2_E * 2)      // 73728 B  (single-A: Ah,Bh)

// Split-A mainloop (Ah+Al vs Bh)
#define GEMM_MAINLOOP(Ah, Al, Bh, KDIM)                                            \
    auto load_chunk = [&](int stage, int kc) {                                     \
        _Pragma("unroll")                                                          \
        for (int j = 0; j < 12; ++j) {                                             \
            int s = tid + j * 256;                                                 \
            int tile = s >> 10;                                                    \
            int r = (s >> 3) & 127;                                                \
            int c = s & 7;                                                         \
            const __half* p = (tile == 0) ? Ah : (tile == 1) ? Al : Bh;            \
            int rb = (tile < 2) ? bm : bn;                                         \
            const __half* src = p + (size_t)(rb + r) * (KDIM) + kc + c * 8;        \
            uint32_t dst = sbase + (uint32_t)(stage * STG_E + tile * TILE_E +      \
                                              r * GSTR + c * 8) * 2u;              \
            CP16(dst, src);                                                        \
        }                                                                          \
    };                                                                             \
    const int NC = (KDIM) / 64;                                                    \
    load_chunk(0, 0);                                                              \
    CP_COMMIT();                                                                   \
    for (int i = 0; i < NC; ++i) {                                                 \
        if (i + 1 < NC) {                                                          \
            load_chunk((i + 1) & 1, (i + 1) * 64);                                 \
            CP_COMMIT();                                                           \
            CP_WAIT(1);                                                            \
        } else {                                                                   \
            CP_WAIT(0);                                                            \
        }                                                                          \
        __syncthreads();                                                           \
        const uint32_t sA  = sbase + (uint32_t)((i & 1) * STG_E) * 2u;             \
        const uint32_t dAl = TILE_E * 2u;                                          \
        const uint32_t dB  = 2u * TILE_E * 2u;                                     \
        _Pragma("unroll")                                                          \
        for (int ks = 0; ks < 64; ks += 16) {                                      \
            uint32_t ah[2][4], al[2][4], bh[8][2];                                 \
            _Pragma("unroll")                                                      \
            for (int mt = 0; mt < 2; ++mt) {                                       \
                uint32_t ra = sA + (uint32_t)((wm + mt * 16 + (lane & 15)) * GSTR +\
                                              ks + (lane >> 4) * 8) * 2u;          \
                ldsm4(ah[mt], ra);                                                 \
                ldsm4(al[mt], ra + dAl);                                           \
            }                                                                      \
            _Pragma("unroll")                                                      \
            for (int p = 0; p < 4; ++p) {                                          \
                uint32_t rb = sA + dB + (uint32_t)((wn + p * 16 + (lane & 15)) * GSTR + \
                                                   ks + (lane >> 4) * 8) * 2u;     \
                uint32_t t[4];                                                     \
                ldsm4(t, rb);                                                      \
                bh[2 * p][0] = t[0]; bh[2 * p + 1][0] = t[1];                      \
                bh[2 * p][1] = t[2]; bh[2 * p + 1][1] = t[3];                      \
            }                                                                      \
            _Pragma("unroll")                                                      \
            for (int mt = 0; mt < 2; ++mt)                                         \
                _Pragma("unroll")                                                  \
                for (int nt = 0; nt < 8; ++nt) mma16816(acc[mt][nt], ah[mt], bh[nt]); \
            _Pragma("unroll")                                                      \
            for (int mt = 0; mt < 2; ++mt)                                         \
                _Pragma("unroll")                                                  \
                for (int nt = 0; nt < 8; ++nt) mma16816(acc[mt][nt], al[mt], bh[nt]); \
        }                                                                          \
        __syncthreads();                                                           \
    }

// Single-A mainloop (Ah vs Bh), 2-tile stages
#define GEMM1A_MAINLOOP(Ah, Bh, KDIM)                                              \
    auto load_chunk = [&](int stage, int kc) {                                     \
        _Pragma("unroll")                                                          \
        for (int j = 0; j < 8; ++j) {                                              \
            int s = tid + j * 256;                                                 \
            int tile = s >> 10;                                                    \
            int r = (s >> 3) & 127;                                                \
            int c = s & 7;                                                         \
            const __half* p = (tile == 0) ? Ah : Bh;                               \
            int rb = (tile == 0) ? bm : bn;                                        \
            const __half* src = p + (size_t)(rb + r) * (KDIM) + kc + c * 8;        \
            uint32_t dst = sbase + (uint32_t)(stage * STG2_E + tile * TILE_E +     \
                                              r * GSTR + c * 8) * 2u;              \
            CP16(dst, src);                                                        \
        }                                                                          \
    };                                                                             \
    const int NC = (KDIM) / 64;                                                    \
    load_chunk(0, 0);                                                              \
    CP_COMMIT();                                                                   \
    for (int i = 0; i < NC; ++i) {                                                 \
        if (i + 1 < NC) {                                                          \
            load_chunk((i + 1) & 1, (i + 1) * 64);                                 \
            CP_COMMIT();                                                           \
            CP_WAIT(1);                                                            \
        } else {                                                                   \
            CP_WAIT(0);                                                            \
        }                                                                          \
        __syncthreads();                                                           \
        const uint32_t sA = sbase + (uint32_t)((i & 1) * STG2_E) * 2u;             \
        const uint32_t dB = TILE_E * 2u;                                           \
        _Pragma("unroll")                                                          \
        for (int ks = 0; ks < 64; ks += 16) {                                      \
            uint32_t ah[2][4], bh[8][2];                                           \
            _Pragma("unroll")                                                      \
            for (int mt = 0; mt < 2; ++mt) {                                       \
                uint32_t ra = sA + (uint32_t)((wm + mt * 16 + (lane & 15)) * GSTR +\
                                              ks + (lane >> 4) * 8) * 2u;          \
                ldsm4(ah[mt], ra);                                                 \
            }                                                                      \
            _Pragma("unroll")                                                      \
            for (int p = 0; p < 4; ++p) {                                          \
                uint32_t rb = sA + dB + (uint32_t)((wn + p * 16 + (lane & 15)) * GSTR + \
                                                   ks + (lane >> 4) * 8) * 2u;     \
                uint32_t t[4];                                                     \
                ldsm4(t, rb);                                                      \
                bh[2 * p][0] = t[0]; bh[2 * p + 1][0] = t[1];                      \
                bh[2 * p][1] = t[2]; bh[2 * p + 1][1] = t[3];                      \
            }                                                                      \
            _Pragma("unroll")                                                      \
            for (int mt = 0; mt < 2; ++mt)                                         \
                _Pragma("unroll")                                                  \
                for (int nt = 0; nt < 8; ++nt) mma16816(acc[mt][nt], ah[mt], bh[nt]); \
        }                                                                          \
        __syncthreads();                                                           \
    }

// ---------------------------------------------------------------------------
// GEMM1-Q: q = x @ Wq^T (split-A) + RoPE + scale + hi/lo split epilogue.
// grid (16 heads, 32 m-tiles)
// ---------------------------------------------------------------------------
__global__ __launch_bounds__(256) void gemm1_q_kernel(
    const __half* __restrict__ Ah, const __half* __restrict__ Al,
    const __half* __restrict__ Bh,
    const float* __restrict__ ct, const float* __restrict__ st,
    __half* __restrict__ Qh, __half* __restrict__ Ql)
{
    extern __shared__ __half sm[];
    const uint32_t sbase = smem_u32(sm);
    const int tid  = threadIdx.x;
    const int lane = tid & 31;
    const int wid  = tid >> 5;
    const int bm = blockIdx.y * 128;
    const int bn = blockIdx.x * 128;          // q region of W_qkv^T
    const int wm = (wid & 3) * 32;
    const int wn = (wid >> 2) * 64;

    float acc[2][8][4];
#pragma unroll
    for (int mt = 0; mt < 2; ++mt)
#pragma unroll
        for (int nt = 0; nt < 8; ++nt)
#pragma unroll
            for (int v = 0; v < 4; ++v) acc[mt][nt][v] = 0.f;

    GEMM_MAINLOOP(Ah, Al, Bh, D_)

    float* sf = (float*)sm;
#pragma unroll
    for (int mt = 0; mt < 2; ++mt) {
        int row = wm + mt * 16 + (lane >> 2);
#pragma unroll
        for (int nt = 0; nt < 8; ++nt) {
            int col = wn + nt * 8 + (lane & 3) * 2;
            sf[row * 129 + col]           = acc[mt][nt][0];
            sf[row * 129 + col + 1]       = acc[mt][nt][1];
            sf[(row + 8) * 129 + col]     = acc[mt][nt][2];
            sf[(row + 8) * 129 + col + 1] = acc[mt][nt][3];
        }
    }
    __syncthreads();

    const int h  = blockIdx.x;
    const int b  = bm >> 11;
    const int s0 = bm & (S_ - 1);

    for (int idx = tid; idx < 128 * 64; idx += 256) {
        int r = idx >> 6, d = idx & 63;
        float lo_v = sf[r * 129 + d];
        float hi_v = sf[r * 129 + d + 64];
        int s = s0 + r;
        float c  = ct[(s << 6) + d];
        float sn = st[(s << 6) + d];
        float e0 = (lo_v * c - hi_v * sn) * 0.08838834764831845f;
        float e1 = (hi_v * c + lo_v * sn) * 0.08838834764831845f;
        size_t dst = ((size_t)(b * H_ + h) * S_ + s) * HD_ + d;
        __half h0 = __float2half_rn(e0);
        __half h1 = __float2half_rn(e1);
        Qh[dst]      = h0;
        Qh[dst + 64] = h1;
        Ql[dst]      = __float2half_rn(e0 - __half2float(h0));
        Ql[dst + 64] = __float2half_rn(e1 - __half2float(h1));
    }
}

// ---------------------------------------------------------------------------
// GEMM1-KV: k,v = x @ Wkv^T (single-A; outputs are fp16-rounded anyway)
// grid (32, 32): x = kind*16 + head. K: RoPE+round. V: transpose+round.
// ---------------------------------------------------------------------------
__global__ __launch_bounds__(256) void gemm1_kv_kernel(
    const __half* __restrict__ Ah, const __half* __restrict__ Bh,
    const float* __restrict__ ct, const float* __restrict__ st,
    __half* __restrict__ Kh, __half* __restrict__ Vth)
{
    extern __shared__ __half sm[];
    const uint32_t sbase = smem_u32(sm);
    const int tid  = threadIdx.x;
    const int lane = tid & 31;
    const int wid  = tid >> 5;
    const int bm = blockIdx.y * 128;
    const int bn = DM_ + blockIdx.x * 128;    // k/v region of W_qkv^T
    const int wm = (wid & 3) * 32;
    const int wn = (wid >> 2) * 64;

    float acc[2][8][4];
#pragma unroll
    for (int mt = 0; mt < 2; ++mt)
#pragma unroll
        for (int nt = 0; nt < 8; ++nt)
#pragma unroll
            for (int v = 0; v < 4; ++v) acc[mt][nt][v] = 0.f;

    GEMM1A_MAINLOOP(Ah, Bh, D_)

    float* sf = (float*)sm;
#pragma unroll
    for (int mt = 0; mt < 2; ++mt) {
        int row = wm + mt * 16 + (lane >> 2);
#pragma unroll
        for (int nt = 0; nt < 8; ++nt) {
            int col = wn + nt * 8 + (lane & 3) * 2;
            sf[row * 129 + col]           = acc[mt][nt][0];
            sf[row * 129 + col + 1]       = acc[mt][nt][1];
            sf[(row + 8) * 129 + col]     = acc[mt][nt][2];
            sf[(row + 8) * 129 + col + 1] = acc[mt][nt][3];
        }
    }
    __syncthreads();

    const int kind = blockIdx.x >> 4;   // 0=k 1=v
    const int h    = blockIdx.x & 15;
    const int b    = bm >> 11;
    const int s0   = bm & (S_ - 1);

    if (kind == 0) {
        for (int idx = tid; idx < 128 * 64; idx += 256) {
            int r = idx >> 6, d = idx & 63;
            float lo_v = sf[r * 129 + d];
            float hi_v = sf[r * 129 + d + 64];
            int s = s0 + r;
            float c  = ct[(s << 6) + d];
            float sn = st[(s << 6) + d];
            size_t dst = ((size_t)(b * H_ + h) * S_ + s) * HD_ + d;
            Kh[dst]      = __float2half_rn(lo_v * c - hi_v * sn);
            Kh[dst + 64] = __float2half_rn(hi_v * c + lo_v * sn);
        }
    } else {
        __half* vdst = Vth + (size_t)(b * H_ + h) * HD_ * S_;
        for (int idx = tid; idx < 128 * 128; idx += 256) {
            int r = idx & 127, d = idx >> 7;
            vdst[(size_t)d * S_ + s0 + r] = __float2half_rn(sf[r * 129 + d]);
        }
    }
}

// ---------------------------------------------------------------------------
// GEMM2: out = O @ W_o^T — single-A (O rounded)
// ---------------------------------------------------------------------------
__global__ __launch_bounds__(256) void gemm2_mma_kernel(
    const __half* __restrict__ Ah, const __half* __restrict__ Bh,
    float* __restrict__ C, int M, int N, int K)
{
    extern __shared__ __half sm[];
    const uint32_t sbase = smem_u32(sm);
    const int tid  = threadIdx.x;
    const int lane = tid & 31;
    const int wid  = tid >> 5;
    const int bm = blockIdx.y * 128;
    const int bn = blockIdx.x * 128;
    const int wm = (wid & 3) * 32;
    const int wn = (wid >> 2) * 64;

    float acc[2][8][4];
#pragma unroll
    for (int mt = 0; mt < 2; ++mt)
#pragma unroll
        for (int nt = 0; nt < 8; ++nt)
#pragma unroll
            for (int v = 0; v < 4; ++v) acc[mt][nt][v] = 0.f;

    GEMM1A_MAINLOOP(Ah, Bh, K)

#pragma unroll
    for (int mt = 0; mt < 2; ++mt) {
        int row = bm + wm + mt * 16 + (lane >> 2);
#pragma unroll
        for (int nt = 0; nt < 8; ++nt) {
            int col = bn + wn + nt * 8 + (lane & 3) * 2;
            *(float2*)&C[(size_t)row * N + col] =
                make_float2(acc[mt][nt][0], acc[mt][nt][1]);
            *(float2*)&C[(size_t)(row + 8) * N + col] =
                make_float2(acc[mt][nt][2], acc[mt][nt][3]);
        }
    }
}

// ---------------------------------------------------------------------------
// fp32 -> fp16 hi/lo split (x only)
// ---------------------------------------------------------------------------
__global__ void conv_split_kernel(const float* __restrict__ X,
                                  __half* __restrict__ Xh,
                                  __half* __restrict__ Xl, int n4)
{
    int i = blockIdx.x * blockDim.x + threadIdx.x;
    if (i >= n4) return;
    float4 v = *(const float4*)(X + (size_t)i * 4);
    __half2 h01 = __floats2half2_rn(v.x, v.y);
    __half2 h23 = __floats2half2_rn(v.z, v.w);
    float2 f01 = __half22float2(h01);
    float2 f23 = __half22float2(h23);
    __half2 l01 = __floats2half2_rn(v.x - f01.x, v.y - f01.y);
    __half2 l23 = __floats2half2_rn(v.z - f23.x, v.w - f23.y);
    *(__half2*)(Xh + (size_t)i * 4)     = h01;
    *(__half2*)(Xh + (size_t)i * 4 + 2) = h23;
    *(__half2*)(Xl + (size_t)i * 4)     = l01;
    *(__half2*)(Xl + (size_t)i * 4 + 2) = l23;
}

// ---------------------------------------------------------------------------
// fp32 W[R,C] -> transposed fp16 (rounded) T[C,R]
// ---------------------------------------------------------------------------
__global__ __launch_bounds__(256) void conv_tround_kernel(
    const float* __restrict__ W, int R, int C, __half* __restrict__ Th)
{
    __shared__ float t[32][33];
    const int c0 = blockIdx.x * 32, r0 = blockIdx.y * 32;
    const int tx = threadIdx.x & 31, ty = threadIdx.x >> 5;
#pragma unroll
    for (int i = 0; i < 32; i += 8)
        t[ty + i][tx] = W[(size_t)(r0 + ty + i) * C + c0 + tx];
    __syncthreads();
#pragma unroll
    for (int i = 0; i < 32; i += 8)
        Th[(size_t)(c0 + ty + i) * R + r0 + tx] = __float2half_rn(t[tx][ty + i]);
}

// ---------------------------------------------------------------------------
// RoPE table
// ---------------------------------------------------------------------------
__global__ void rope_table_kernel(float* __restrict__ ct, float* __restrict__ st)
{
    int idx = blockIdx.x * blockDim.x + threadIdx.x;
    if (idx >= S_ * 64) return;
    int d = idx & 63;
    int s = idx >> 6;
    float inv_freq = 1.0f / powf(10000.0f, (float)d * (1.0f / 64.0f));
    float ang = (float)s * inv_freq;
    ct[idx] = (float)cos((double)ang);
    st[idx] = (float)sin((double)ang);
}

// ---------------------------------------------------------------------------
// Flash attention: QK split-A (2 MMA), PV rounded-P (1 MMA).
// ---------------------------------------------------------------------------
#define QSTR 136
#define VSTR 72
#define QH_OFF 0u
#define QL_OFF 34816u
#define KV_BASE 69632u
#define KV_STG  35840u
#define KH_R 0u
#define VH_R 17408u
#define ATT_SMEM (KV_BASE + 2u * KV_STG)   // 141312 bytes

__global__ __launch_bounds__(256) void attn_mma_kernel(
    const __half* __restrict__ Qh, const __half* __restrict__ Ql,
    const __half* __restrict__ Kh, const __half* __restrict__ Vth,
    __half* __restrict__ Oh)
{
    extern __shared__ char asm_[];
    const uint32_t sb = smem_u32(asm_);
    const int tid  = threadIdx.x;
    const int lane = tid & 31;
    const int wid  = tid >> 5;
    const int qb = (int)(gridDim.x - 1) - (int)blockIdx.x;   // heavy first
    const int h  = blockIdx.y;
    const int b  = blockIdx.z;
    const int bh = b * H_ + h;
    const int q0 = qb * 128;
    const int wq = wid * 16;

    const __half* k_h = Kh + ((size_t)bh * S_) * HD_;
    const __half* v_h = Vth + (size_t)bh * HD_ * S_;

    {
        const __half* q_h = Qh + ((size_t)bh * S_ + q0) * HD_;
        const __half* q_l = Ql + ((size_t)bh * S_ + q0) * HD_;
#pragma unroll
        for (int j = 0; j < 16; ++j) {
            int s = tid + j * 256;
            int hi = s < 2048;
            int u = s & 2047;
            int r = u >> 4, c = u & 15;
            const __half* src = (hi ? q_h : q_l) + (size_t)r * HD_ + c * 8;
            CP16(sb + (hi ? QH_OFF : QL_OFF) + (uint32_t)(r * QSTR + c * 8) * 2u, src);
        }
    }
    CP_COMMIT();

    auto load_kv = [&](int stage, int kv0) {
        const uint32_t st = KV_BASE + (uint32_t)stage * KV_STG;
#pragma unroll
        for (int j = 0; j < 8; ++j) {
            int s = tid + j * 256;
            if (s < 1024) {
                int r = s >> 4, c = s & 15;
                const __half* src = k_h + (size_t)(kv0 + r) * HD_ + c * 8;
                CP16(sb + st + KH_R + (uint32_t)(r * QSTR + c * 8) * 2u, src);
            } else {
                int u = s - 1024;
                int r = u >> 3, c = u & 7;
                const __half* src = v_h + (size_t)r * S_ + kv0 + c * 8;
                CP16(sb + st + VH_R + (uint32_t)(r * VSTR + c * 8) * 2u, src);
            }
        }
    };

    const int nkb = 2 * (qb + 1);
    load_kv(0, 0);
    CP_COMMIT();

    float acc[16][4];
#pragma unroll
    for (int nt = 0; nt < 16; ++nt)
#pragma unroll
        for (int v = 0; v < 4; ++v) acc[nt][v] = 0.f;
    float m0 = -INFINITY, m1 = -INFINITY, l0 = 0.f, l1 = 0.f;

    const int r0 = lane >> 2;
    const int rg0 = q0 + wq + r0;

    for (int kb = 0; kb < nkb; ++kb) {
        const int kv0 = kb * 64;
        __syncthreads();
        if (kb + 1 < nkb) {
            load_kv((kb + 1) & 1, kv0 + 64);
            CP_COMMIT();
            CP_WAIT(1);
        } else {
            CP_WAIT(0);
        }
        __syncthreads();

        const uint32_t skv = sb + KV_BASE + (uint32_t)(kb & 1) * KV_STG;

        float sc[8][4];
#pragma unroll
        for (int nt = 0; nt < 8; ++nt)
#pragma unroll
            for (int v = 0; v < 4; ++v) sc[nt][v] = 0.f;

#pragma unroll
        for (int ks = 0; ks < 8; ++ks) {
            uint32_t a_h[4], a_l[4], b_h[8][2];
            uint32_t ra = sb + QH_OFF + (uint32_t)((wq + (lane & 15)) * QSTR +
                                                   ks * 16 + (lane >> 4) * 8) * 2u;
            ldsm4(a_h, ra);
            ldsm4(a_l, ra + QL_OFF);
#pragma unroll
            for (int p = 0; p < 4; ++p) {
                uint32_t rb = skv + KH_R + (uint32_t)((p * 16 + (lane & 15)) * QSTR +
                                                      ks * 16 + (lane >> 4) * 8) * 2u;
                uint32_t t[4];
                ldsm4(t, rb);
                b_h[2 * p][0] = t[0]; b_h[2 * p + 1][0] = t[1];
                b_h[2 * p][1] = t[2]; b_h[2 * p + 1][1] = t[3];
            }
#pragma unroll
            for (int nt = 0; nt < 8; ++nt) mma16816(sc[nt], a_h, b_h[nt]);
#pragma unroll
            for (int nt = 0; nt < 8; ++nt) mma16816(sc[nt], a_l, b_h[nt]);
        }

        if (kv0 + 63 > q0 + wq) {
#pragma unroll
            for (int nt = 0; nt < 8; ++nt) {
                int c0 = kv0 + nt * 8 + (lane & 3) * 2;
                if (c0     > rg0)     sc[nt][0] = -INFINITY;
                if (c0 + 1 > rg0)     sc[nt][1] = -INFINITY;
                if (c0     > rg0 + 8) sc[nt][2] = -INFINITY;
                if (c0 + 1 > rg0 + 8) sc[nt][3] = -INFINITY;
            }
        }

        float mx0 = -INFINITY, mx1 = -INFINITY;
#pragma unroll
        for (int nt = 0; nt < 8; ++nt) {
            mx0 = fmaxf(mx0, fmaxf(sc[nt][0], sc[nt][1]));
            mx1 = fmaxf(mx1, fmaxf(sc[nt][2], sc[nt][3]));
        }
        mx0 = fmaxf(mx0, __shfl_xor_sync(0xffffffffu, mx0, 1));
        mx0 = fmaxf(mx0, __shfl_xor_sync(0xffffffffu, mx0, 2));
        mx1 = fmaxf(mx1, __shfl_xor_sync(0xffffffffu, mx1, 1));
        mx1 = fmaxf(mx1, __shfl_xor_sync(0xffffffffu, mx1, 2));
        float m0n = fmaxf(m0, mx0), m1n = fmaxf(m1, mx1);
        float al0 = __expf(m0 - m0n), al1 = __expf(m1 - m1n);
        float ps0 = 0.f, ps1 = 0.f;
#pragma unroll
        for (int nt = 0; nt < 8; ++nt) {
            sc[nt][0] = __expf(sc[nt][0] - m0n);
            sc[nt][1] = __expf(sc[nt][1] - m0n);
            sc[nt][2] = __expf(sc[nt][2] - m1n);
            sc[nt][3] = __expf(sc[nt][3] - m1n);
            ps0 += sc[nt][0] + sc[nt][1];
            ps1 += sc[nt][2] + sc[nt][3];
        }
        ps0 += __shfl_xor_sync(0xffffffffu, ps0, 1);
        ps0 += __shfl_xor_sync(0xffffffffu, ps0, 2);
        ps1 += __shfl_xor_sync(0xffffffffu, ps1, 1);
        ps1 += __shfl_xor_sync(0xffffffffu, ps1, 2);
        l0 = l0 * al0 + ps0;
        l1 = l1 * al1 + ps1;
        m0 = m0n; m1 = m1n;
#pragma unroll
        for (int nt = 0; nt < 16; ++nt) {
            acc[nt][0] *= al0; acc[nt][1] *= al0;
            acc[nt][2] *= al1; acc[nt][3] *= al1;
        }

        uint32_t phk[4][4];
#pragma unroll
        for (int kt = 0; kt < 4; ++kt) {
#pragma unroll
            for (int half = 0; half < 2; ++half) {
                int j = 2 * kt + half;
                phk[kt][half * 2 + 0] = pack_h2(sc[j][0], sc[j][1]);
                phk[kt][half * 2 + 1] = pack_h2(sc[j][2], sc[j][3]);
            }
        }

#pragma unroll
        for (int kt = 0; kt < 4; ++kt) {
#pragma unroll
            for (int hlf = 0; hlf < 2; ++hlf) {
                uint32_t bvh[8][2];
#pragma unroll
                for (int p = 0; p < 4; ++p) {
                    uint32_t rb = skv + VH_R +
                        (uint32_t)((hlf * 64 + p * 16 + (lane & 15)) * VSTR +
                                   kt * 16 + (lane >> 4) * 8) * 2u;
                    uint32_t t[4];
                    ldsm4(t, rb);
                    bvh[2 * p][0] = t[0]; bvh[2 * p + 1][0] = t[1];
                    bvh[2 * p][1] = t[2]; bvh[2 * p + 1][1] = t[3];
                }
#pragma unroll
                for (int nt = 0; nt < 8; ++nt) mma16816(acc[hlf * 8 + nt], phk[kt], bvh[nt]);
            }
        }
    }

    float inv0 = 1.f / l0, inv1 = 1.f / l1;
    size_t tok0 = (size_t)b * S_ + q0 + wq + r0;
#pragma unroll
    for (int nt = 0; nt < 16; ++nt) {
        int col = h * HD_ + nt * 8 + (lane & 3) * 2;
        *(uint32_t*)&Oh[tok0 * DM_ + col] =
            pack_h2(acc[nt][0] * inv0, acc[nt][1] * inv0);
        *(uint32_t*)&Oh[(tok0 + 8) * DM_ + col] =
            pack_h2(acc[nt][2] * inv1, acc[nt][3] * inv1);
    }
}

// ---------------------------------------------------------------------------
// Launch
// ---------------------------------------------------------------------------
extern "C" void kernel_launch(void* const* d_in, const int* in_sizes, int n_in,
                              void* d_out, int out_size)
{
    (void)in_sizes; (void)n_in; (void)out_size;
    const float* x     = (const float*)d_in[0];
    const float* W_qkv = (const float*)d_in[1];
    const float* W_o   = (const float*)d_in[2];
    float* out = (float*)d_out;

    float *ct, *st;
    __half *Ah, *Al, *Bh, *Woh, *Qh, *Ql, *Kh, *Vth;
    cudaGetSymbolAddress((void**)&ct,   g_cos);
    cudaGetSymbolAddress((void**)&st,   g_sin);
    cudaGetSymbolAddress((void**)&Ah,   g_Ah);
    cudaGetSymbolAddress((void**)&Al,   g_Al);
    cudaGetSymbolAddress((void**)&Bh,   g_Bh);
    cudaGetSymbolAddress((void**)&Woh,  g_Woh);
    cudaGetSymbolAddress((void**)&Qh,   g_Qh);
    cudaGetSymbolAddress((void**)&Ql,   g_Ql);
    cudaGetSymbolAddress((void**)&Kh,   g_Kh);
    cudaGetSymbolAddress((void**)&Vth,  g_Vth);

    cudaFuncSetAttribute(gemm1_q_kernel,
                         cudaFuncAttributeMaxDynamicSharedMemorySize, GEMM_SMEM);
    cudaFuncSetAttribute(gemm1_kv_kernel,
                         cudaFuncAttributeMaxDynamicSharedMemorySize, GEMM2_SMEM);
    cudaFuncSetAttribute(gemm2_mma_kernel,
                         cudaFuncAttributeMaxDynamicSharedMemorySize, GEMM2_SMEM);
    cudaFuncSetAttribute(attn_mma_kernel,
                         cudaFuncAttributeMaxDynamicSharedMemorySize, ATT_SMEM);

    rope_table_kernel<<<(S_ * 64 + 255) / 256, 256>>>(ct, st);

    conv_split_kernel<<<(M_TOK * D_ / 4 + 255) / 256, 256>>>(x, Ah, Al, M_TOK * D_ / 4);
    conv_tround_kernel<<<dim3(QKV_N / 32, D_ / 32), 256>>>(W_qkv, D_, QKV_N, Bh);
    conv_tround_kernel<<<dim3(DM_ / 32, D_ / 32), 256>>>(W_o, DM_, DM_, Woh);

    // q projection (split-A, error-compensated) + RoPE epilogue
    gemm1_q_kernel<<<dim3(H_, M_TOK / 128), 256, GEMM_SMEM>>>(
        Ah, Al, Bh, ct, st, Qh, Ql);

    // k,v projection (single-A; outputs rounded anyway) + RoPE/transpose
    gemm1_kv_kernel<<<dim3(2 * H_, M_TOK / 128), 256, GEMM2_SMEM>>>(
        Ah, Bh, ct, st, Kh, Vth);

    // causal flash attention -> writes Oh into g_Ah (GEMM2 operand)
    attn_mma_kernel<<<dim3(S_ / 128, H_, B_), 256, ATT_SMEM>>>(
        Qh, Ql, Kh, Vth, Ah);

    // out = O @ W_o (single-A GEMM)
    gemm2_mma_kernel<<<dim3(DM_ / 128, M_TOK / 128), 256, GEMM2_SMEM>>>(
        Ah, Woh, out, M_TOK, DM_, D_);
}